// round 5
// baseline (speedup 1.0000x reference)
#include <cuda_runtime.h>

#define B_   128
#define N_   577
#define DIM_ 1024
#define H_   16
#define D_   64
#define BH_  (B_*H_)

// ---- scratch (static device allocations; no cudaMalloc anywhere) ----
static __device__ float g_w[(size_t)B_*N_*DIM_];       // w = x@Wp^T, later reused as x_delta
static __device__ float g_attn[(size_t)BH_*64*N_];     // attention-1 probs (b,h,64,577)
static __device__ float g_rep[(size_t)BH_*64*64];      // rep (b,h,64,64)
static __device__ float g_out2[(size_t)BH_*64*64];     // attention-2 output

// ============================================================
// NT SGEMM: C[M,1024] = A[M,1024] @ Bm[1024,1024]^T (+bias)
// BM=BN=128, BK=16, 256 threads, 8x8 micro-tile
// ============================================================
__device__ __forceinline__ void sgemm_nt_body(const float* __restrict__ A,
                                              const float* __restrict__ Bm,
                                              const float* __restrict__ bias,
                                              float* __restrict__ C)
{
    __shared__ float As[16][132];
    __shared__ float Bs[16][132];
    const int K = 1024, Nn = 1024;
    const int tid = threadIdx.x;
    const int tx = tid & 15, ty = tid >> 4;
    const int m0 = blockIdx.y * 128, n0 = blockIdx.x * 128;

    float acc[8][8];
#pragma unroll
    for (int i = 0; i < 8; i++)
#pragma unroll
        for (int j = 0; j < 8; j++) acc[i][j] = 0.f;

    for (int k0 = 0; k0 < K; k0 += 16) {
        float4 av[2], bv[2];
#pragma unroll
        for (int l = 0; l < 2; l++) {
            int f = tid + l * 256;            // float4 index 0..511
            int row = f >> 2, kq = f & 3;
            av[l] = *(const float4*)&A[(size_t)(m0 + row) * K + k0 + kq * 4];
            bv[l] = *(const float4*)&Bm[(size_t)(n0 + row) * K + k0 + kq * 4];
        }
        __syncthreads();
#pragma unroll
        for (int l = 0; l < 2; l++) {
            int f = tid + l * 256;
            int row = f >> 2, kq = f & 3;
            As[kq*4+0][row] = av[l].x; As[kq*4+1][row] = av[l].y;
            As[kq*4+2][row] = av[l].z; As[kq*4+3][row] = av[l].w;
            Bs[kq*4+0][row] = bv[l].x; Bs[kq*4+1][row] = bv[l].y;
            Bs[kq*4+2][row] = bv[l].z; Bs[kq*4+3][row] = bv[l].w;
        }
        __syncthreads();
#pragma unroll
        for (int k = 0; k < 16; k++) {
            float4 a0 = *(float4*)&As[k][4*ty];
            float4 a1 = *(float4*)&As[k][64 + 4*ty];
            float4 b0 = *(float4*)&Bs[k][4*tx];
            float4 b1 = *(float4*)&Bs[k][64 + 4*tx];
            float ar[8] = {a0.x,a0.y,a0.z,a0.w,a1.x,a1.y,a1.z,a1.w};
            float br[8] = {b0.x,b0.y,b0.z,b0.w,b1.x,b1.y,b1.z,b1.w};
#pragma unroll
            for (int i = 0; i < 8; i++)
#pragma unroll
                for (int j = 0; j < 8; j++) acc[i][j] += ar[i] * br[j];
        }
    }

    float4 bias0 = make_float4(0,0,0,0), bias1 = make_float4(0,0,0,0);
    if (bias) {
        bias0 = *(const float4*)&bias[n0 + 4*tx];
        bias1 = *(const float4*)&bias[n0 + 64 + 4*tx];
    }
#pragma unroll
    for (int i = 0; i < 8; i++) {
        int m = m0 + ((i < 4) ? (4*ty + i) : (64 + 4*ty + i - 4));
        float4 c0 = make_float4(acc[i][0]+bias0.x, acc[i][1]+bias0.y,
                                acc[i][2]+bias0.z, acc[i][3]+bias0.w);
        float4 c1 = make_float4(acc[i][4]+bias1.x, acc[i][5]+bias1.y,
                                acc[i][6]+bias1.z, acc[i][7]+bias1.w);
        *(float4*)&C[(size_t)m * Nn + n0 + 4*tx]      = c0;
        *(float4*)&C[(size_t)m * Nn + n0 + 64 + 4*tx] = c1;
    }
}

__global__ __launch_bounds__(256, 2) void proj_kernel(const float* __restrict__ x,
                                                      const float* __restrict__ Wp)
{
    sgemm_nt_body(x, Wp, nullptr, g_w);
}

__global__ __launch_bounds__(256, 2) void outproj_kernel(const float* __restrict__ Wo,
                                                         const float* __restrict__ bo,
                                                         float* __restrict__ out)
{
    sgemm_nt_body(g_w, Wo, bo, out);
}

// ============================================================
// 3x3 adaptive mean pool -> rep0 (b,h,64,64)
// token grid 24x24 (cls token dropped), p = py*8+px
// ============================================================
__global__ void pool_kernel()
{
    int idx = blockIdx.x * blockDim.x + threadIdx.x;   // < 128*16*64*64 = 8388608
    int d  = idx & 63;
    int p  = (idx >> 6) & 63;
    int hh = (idx >> 12) & 15;
    int b  = idx >> 16;
    int py = p >> 3, px = p & 7;
    float s = 0.f;
#pragma unroll
    for (int r = 0; r < 3; r++)
#pragma unroll
        for (int c = 0; c < 3; c++) {
            int t = (3*py + r) * 24 + 3*px + c;
            s += g_w[((size_t)b * N_ + t) * DIM_ + hh * 64 + d];
        }
    g_rep[idx] = s * (1.f / 9.f);
}

// ============================================================
// attention-1 scores: S = scale * Q K^T  (Q=rep0 64x64, K=wq 577x64)
// grid (10 key-chunks, 2048 bh), 256 threads, 4x4 micro-tile
// ============================================================
__global__ __launch_bounds__(256) void qk_kernel()
{
    __shared__ float Qt[64][64];   // [d][q]
    __shared__ float Kt[64][64];   // [d][t]
    int bh = blockIdx.y;
    int b = bh >> 4, h = bh & 15;
    int t0 = blockIdx.x * 64;
    int tid = threadIdx.x, tx = tid & 15, ty = tid >> 4;

    const float* repb = g_rep + (size_t)bh * 4096;
#pragma unroll
    for (int l = 0; l < 4; l++) {
        int f = tid + l * 256;         // float4 index 0..1023
        int q = f >> 4, dq = f & 15;
        float4 v = *(const float4*)&repb[q * 64 + dq * 4];
        Qt[dq*4+0][q] = v.x; Qt[dq*4+1][q] = v.y;
        Qt[dq*4+2][q] = v.z; Qt[dq*4+3][q] = v.w;
    }
#pragma unroll
    for (int l = 0; l < 4; l++) {
        int f = tid + l * 256;
        int t = f >> 4, dq = f & 15;
        float4 v = make_float4(0,0,0,0);
        if (t0 + t < N_)
            v = *(const float4*)&g_w[((size_t)b * N_ + t0 + t) * DIM_ + h * 64 + dq * 4];
        Kt[dq*4+0][t] = v.x; Kt[dq*4+1][t] = v.y;
        Kt[dq*4+2][t] = v.z; Kt[dq*4+3][t] = v.w;
    }
    __syncthreads();

    float acc[4][4] = {};
#pragma unroll 16
    for (int d = 0; d < 64; d++) {
        float4 qv = *(float4*)&Qt[d][4*ty];
        float4 kv = *(float4*)&Kt[d][4*tx];
        float qa[4] = {qv.x,qv.y,qv.z,qv.w};
        float ka[4] = {kv.x,kv.y,kv.z,kv.w};
#pragma unroll
        for (int i = 0; i < 4; i++)
#pragma unroll
            for (int j = 0; j < 4; j++) acc[i][j] += qa[i] * ka[j];
    }

    float* S = g_attn + (size_t)bh * 64 * N_;
    const float scale = 0.125f;
#pragma unroll
    for (int i = 0; i < 4; i++) {
        int q = 4*ty + i;
#pragma unroll
        for (int j = 0; j < 4; j++) {
            int t = t0 + 4*tx + j;
            if (t < N_) S[(size_t)q * N_ + t] = acc[i][j] * scale;
        }
    }
}

// ============================================================
// softmax over last dim (577), in-place on g_attn. block per bh.
// ============================================================
__global__ __launch_bounds__(256) void softmax_kernel()
{
    int bh = blockIdx.x;
    int w = threadIdx.x >> 5, lane = threadIdx.x & 31;
    for (int rr = 0; rr < 8; rr++) {
        int q = w * 8 + rr;
        float* p = g_attn + (size_t)bh * 64 * N_ + (size_t)q * N_;
        float v[19];
        float m = -INFINITY;
#pragma unroll
        for (int i = 0; i < 19; i++) {
            int idx = i * 32 + lane;
            v[i] = (idx < N_) ? p[idx] : -INFINITY;
            m = fmaxf(m, v[i]);
        }
#pragma unroll
        for (int o = 16; o > 0; o >>= 1) m = fmaxf(m, __shfl_xor_sync(0xffffffffu, m, o));
        float s = 0.f;
#pragma unroll
        for (int i = 0; i < 19; i++) { v[i] = __expf(v[i] - m); s += v[i]; }
#pragma unroll
        for (int o = 16; o > 0; o >>= 1) s += __shfl_xor_sync(0xffffffffu, s, o);
        float inv = 1.f / s;
#pragma unroll
        for (int i = 0; i < 19; i++) {
            int idx = i * 32 + lane;
            if (idx < N_) p[idx] = v[i] * inv;
        }
    }
}

// ============================================================
// rep_delta = P @ V;  rep += step_rep * rep_delta.  block per bh.
// ============================================================
__global__ __launch_bounds__(256) void pv_kernel(const float* __restrict__ step_rep)
{
    __shared__ float Ps[64][68];   // [t_local][q]
    __shared__ float Vs[64][64];   // [t_local][d]
    int bh = blockIdx.x, b = bh >> 4, h = bh & 15;
    int tid = threadIdx.x, tx = tid & 15, ty = tid >> 4;
    const float* P = g_attn + (size_t)bh * 64 * N_;

    float acc[4][4] = {};
    for (int t0 = 0; t0 < N_; t0 += 64) {
        __syncthreads();
#pragma unroll
        for (int l = 0; l < 16; l++) {
            int f = tid + l * 256;
            int tl = f & 63, q = f >> 6;
            Ps[tl][q] = (t0 + tl < N_) ? P[(size_t)q * N_ + t0 + tl] : 0.f;
        }
#pragma unroll
        for (int l = 0; l < 4; l++) {
            int f = tid + l * 256;
            int t = f >> 4, dq = f & 15;
            float4 v = make_float4(0,0,0,0);
            if (t0 + t < N_)
                v = *(const float4*)&g_w[((size_t)b * N_ + t0 + t) * DIM_ + h * 64 + dq * 4];
            *(float4*)&Vs[t][dq * 4] = v;
        }
        __syncthreads();
#pragma unroll 16
        for (int t = 0; t < 64; t++) {
            float4 pv = *(float4*)&Ps[t][4*ty];
            float4 vv = *(float4*)&Vs[t][4*tx];
            float pa[4] = {pv.x,pv.y,pv.z,pv.w};
            float va[4] = {vv.x,vv.y,vv.z,vv.w};
#pragma unroll
            for (int i = 0; i < 4; i++)
#pragma unroll
                for (int j = 0; j < 4; j++) acc[i][j] += pa[i] * va[j];
        }
    }

    float step = step_rep[h];
    float* R = g_rep + (size_t)bh * 4096;
#pragma unroll
    for (int i = 0; i < 4; i++) {
        int q = 4*ty + i;
        float4 old = *(float4*)&R[q * 64 + 4*tx];
        old.x += step * acc[i][0]; old.y += step * acc[i][1];
        old.z += step * acc[i][2]; old.w += step * acc[i][3];
        *(float4*)&R[q * 64 + 4*tx] = old;
    }
}

// ============================================================
// attention-2 (self-attn of rep, all in one block per bh)
// ============================================================
__global__ __launch_bounds__(256) void attn2_kernel()
{
    __shared__ float Rt[64][64];   // [d][q]
    __shared__ float Rn[64][64];   // [k][d]
    __shared__ float Ss[64][64];   // [q][k] -> P after softmax
    int bh = blockIdx.x;
    int tid = threadIdx.x, tx = tid & 15, ty = tid >> 4;
    const float* R = g_rep + (size_t)bh * 4096;

#pragma unroll
    for (int l = 0; l < 4; l++) {
        int f = tid + l * 256;
        int q = f >> 4, dq = f & 15;
        float4 v = *(const float4*)&R[q * 64 + dq * 4];
        *(float4*)&Rn[q][dq * 4] = v;
        Rt[dq*4+0][q] = v.x; Rt[dq*4+1][q] = v.y;
        Rt[dq*4+2][q] = v.z; Rt[dq*4+3][q] = v.w;
    }
    __syncthreads();

    float acc[4][4] = {};
#pragma unroll 16
    for (int d = 0; d < 64; d++) {
        float4 qv = *(float4*)&Rt[d][4*ty];
        float4 kv = *(float4*)&Rt[d][4*tx];
        float qa[4] = {qv.x,qv.y,qv.z,qv.w};
        float ka[4] = {kv.x,kv.y,kv.z,kv.w};
#pragma unroll
        for (int i = 0; i < 4; i++)
#pragma unroll
            for (int j = 0; j < 4; j++) acc[i][j] += qa[i] * ka[j];
    }
    const float scale = 0.125f;
#pragma unroll
    for (int i = 0; i < 4; i++)
        *(float4*)&Ss[4*ty + i][4*tx] = make_float4(acc[i][0]*scale, acc[i][1]*scale,
                                                    acc[i][2]*scale, acc[i][3]*scale);
    __syncthreads();

    // softmax over 64 cols, 8 warps x 8 rows
    {
        int w = tid >> 5, lane = tid & 31;
        for (int rr = 0; rr < 8; rr++) {
            int q = w * 8 + rr;
            float v0 = Ss[q][lane], v1 = Ss[q][32 + lane];
            float m = fmaxf(v0, v1);
#pragma unroll
            for (int o = 16; o > 0; o >>= 1) m = fmaxf(m, __shfl_xor_sync(0xffffffffu, m, o));
            v0 = __expf(v0 - m); v1 = __expf(v1 - m);
            float s = v0 + v1;
#pragma unroll
            for (int o = 16; o > 0; o >>= 1) s += __shfl_xor_sync(0xffffffffu, s, o);
            float inv = 1.f / s;
            Ss[q][lane] = v0 * inv; Ss[q][32 + lane] = v1 * inv;
        }
    }
    __syncthreads();

    float acc2[4][4] = {};
#pragma unroll 16
    for (int k = 0; k < 64; k++) {
        float pv[4];
#pragma unroll
        for (int i = 0; i < 4; i++) pv[i] = Ss[4*ty + i][k];
        float4 rv = *(float4*)&Rn[k][4*tx];
        float ra[4] = {rv.x,rv.y,rv.z,rv.w};
#pragma unroll
        for (int i = 0; i < 4; i++)
#pragma unroll
            for (int j = 0; j < 4; j++) acc2[i][j] += pv[i] * ra[j];
    }
    float* O = g_out2 + (size_t)bh * 4096;
#pragma unroll
    for (int i = 0; i < 4; i++)
        *(float4*)&O[(4*ty + i) * 64 + 4*tx] = make_float4(acc2[i][0], acc2[i][1],
                                                           acc2[i][2], acc2[i][3]);
}

// ============================================================
// x_delta = step_x * (attn^T @ out2), written back into g_w as (b,n,c)
// grid (10 t-chunks, 2048 bh)
// ============================================================
__global__ __launch_bounds__(256) void xdelta_kernel(const float* __restrict__ step_x)
{
    __shared__ float Ap[64][64];   // [p][t_local]
    __shared__ float Os[64][64];   // [p][d]
    int bh = blockIdx.y, b = bh >> 4, h = bh & 15;
    int t0 = blockIdx.x * 64;
    int tid = threadIdx.x, tx = tid & 15, ty = tid >> 4;
    const float* P  = g_attn + (size_t)bh * 64 * N_;
    const float* O2 = g_out2 + (size_t)bh * 4096;

#pragma unroll
    for (int l = 0; l < 16; l++) {
        int f = tid + l * 256;
        int tl = f & 63, p = f >> 6;
        Ap[p][tl] = (t0 + tl < N_) ? P[(size_t)p * N_ + t0 + tl] : 0.f;
    }
#pragma unroll
    for (int l = 0; l < 4; l++) {
        int f = tid + l * 256;
        int p = f >> 4, dq = f & 15;
        *(float4*)&Os[p][dq * 4] = *(const float4*)&O2[p * 64 + dq * 4];
    }
    __syncthreads();

    float acc[4][4] = {};
#pragma unroll 16
    for (int p = 0; p < 64; p++) {
        float4 av = *(float4*)&Ap[p][4*ty];   // components: t rows
        float4 ov = *(float4*)&Os[p][4*tx];   // components: d cols
        float aa[4] = {av.x,av.y,av.z,av.w};
        float oa[4] = {ov.x,ov.y,ov.z,ov.w};
#pragma unroll
        for (int i = 0; i < 4; i++)
#pragma unroll
            for (int j = 0; j < 4; j++) acc[i][j] += aa[i] * oa[j];
    }

    float step = step_x[h];
#pragma unroll
    for (int i = 0; i < 4; i++) {
        int t = t0 + 4*ty + i;
        if (t < N_) {
            float4 o = make_float4(step*acc[i][0], step*acc[i][1],
                                   step*acc[i][2], step*acc[i][3]);
            *(float4*)&g_w[((size_t)b * N_ + t) * DIM_ + h * 64 + 4*tx] = o;
        }
    }
}

// ============================================================
extern "C" void kernel_launch(void* const* d_in, const int* in_sizes, int n_in,
                              void* d_out, int out_size)
{
    (void)in_sizes; (void)n_in; (void)out_size;
    const float* x        = (const float*)d_in[0];
    const float* W_proj   = (const float*)d_in[1];
    const float* step_x   = (const float*)d_in[2];
    const float* step_rep = (const float*)d_in[3];
    const float* W_out    = (const float*)d_in[4];
    const float* b_out    = (const float*)d_in[5];
    float* out = (float*)d_out;

    dim3 gemm_grid(DIM_ / 128, (B_ * N_) / 128);   // (8, 577); M=73856 divisible by 128

    proj_kernel<<<gemm_grid, 256>>>(x, W_proj);
    pool_kernel<<<(B_*H_*64*64) / 256, 256>>>();
    qk_kernel<<<dim3(10, BH_), 256>>>();
    softmax_kernel<<<BH_, 256>>>();
    pv_kernel<<<BH_, 256>>>(step_rep);
    attn2_kernel<<<BH_, 256>>>();
    xdelta_kernel<<<dim3(10, BH_), 256>>>(step_x);
    outproj_kernel<<<gemm_grid, 256>>>(W_out, b_out, out);
}

// round 14
// speedup vs baseline: 1.6058x; 1.6058x over previous
#include <cuda_runtime.h>
#include <cuda_fp16.h>
#include <stdint.h>

#define B_   128
#define N_   577
#define DIM_ 1024
#define H_   16
#define BH_  (B_*H_)
#define M_ROWS (B_*N_)   // 73856

// ---- scratch (static device allocations; no cudaMalloc anywhere) ----
static __device__ float g_w[(size_t)M_ROWS*DIM_];      // w = x@Wp^T, later x_delta
static __device__ float g_attn[(size_t)BH_*64*N_];     // attention-1 probs
static __device__ float g_rep[(size_t)BH_*64*64];      // rep
static __device__ float g_out2[(size_t)BH_*64*64];     // attention-2 output
static __device__ __half g_ahi[(size_t)M_ROWS*DIM_];   // fp16 hi of A operand
static __device__ __half g_alo[(size_t)M_ROWS*DIM_];   // fp16 lo residual of A
static __device__ __half g_whi[(size_t)DIM_*DIM_];     // fp16 hi of weight
static __device__ __half g_wlo[(size_t)DIM_*DIM_];     // fp16 lo residual

// ============================================================
// warp-MMA helpers (plain sm_103-legal PTX: ldmatrix + mma.sync fp16)
// ============================================================
__device__ __forceinline__ uint32_t smem_u32(const void* p) {
    return (uint32_t)__cvta_generic_to_shared(p);
}
__device__ __forceinline__ void ldsm_x4(uint32_t* r, uint32_t addr) {
    asm volatile("ldmatrix.sync.aligned.m8n8.x4.shared.b16 {%0,%1,%2,%3}, [%4];"
                 : "=r"(r[0]), "=r"(r[1]), "=r"(r[2]), "=r"(r[3]) : "r"(addr));
}
__device__ __forceinline__ void mma_fp16(float* c, const uint32_t* a, const uint32_t* b) {
    asm volatile("mma.sync.aligned.m16n8k16.row.col.f32.f16.f16.f32 "
                 "{%0,%1,%2,%3}, {%4,%5,%6,%7}, {%8,%9}, {%0,%1,%2,%3};"
                 : "+f"(c[0]), "+f"(c[1]), "+f"(c[2]), "+f"(c[3])
                 : "r"(a[0]), "r"(a[1]), "r"(a[2]), "r"(a[3]),
                   "r"(b[0]), "r"(b[1]));
}

// ============================================================
// split: fp32 -> fp16 hi + fp16 lo residual (error ~2^-22 rel)
// ============================================================
__global__ __launch_bounds__(256) void split_a_kernel(const float* __restrict__ src_opt)
{
    const float* src = src_opt ? src_opt : g_w;
    size_t i = (size_t)blockIdx.x * 256 + threadIdx.x;   // one float4 each
    float4 v = ((const float4*)src)[i];
    __half h0 = __float2half(v.x), h1 = __float2half(v.y);
    __half h2 = __float2half(v.z), h3 = __float2half(v.w);
    __half l0 = __float2half(v.x - __half2float(h0));
    __half l1 = __float2half(v.y - __half2float(h1));
    __half l2 = __float2half(v.z - __half2float(h2));
    __half l3 = __float2half(v.w - __half2float(h3));
    __half2 p0 = __halves2half2(h0, h1), p1 = __halves2half2(h2, h3);
    __half2 q0 = __halves2half2(l0, l1), q1 = __halves2half2(l2, l3);
    uint2 uh, ul;
    uh.x = *(unsigned*)&p0; uh.y = *(unsigned*)&p1;
    ul.x = *(unsigned*)&q0; ul.y = *(unsigned*)&q1;
    ((uint2*)g_ahi)[i] = uh;
    ((uint2*)g_alo)[i] = ul;
}

__global__ __launch_bounds__(256) void split_w_kernel(const float* __restrict__ src)
{
    size_t i = (size_t)blockIdx.x * 256 + threadIdx.x;
    float4 v = ((const float4*)src)[i];
    __half h0 = __float2half(v.x), h1 = __float2half(v.y);
    __half h2 = __float2half(v.z), h3 = __float2half(v.w);
    __half l0 = __float2half(v.x - __half2float(h0));
    __half l1 = __float2half(v.y - __half2float(h1));
    __half l2 = __float2half(v.z - __half2float(h2));
    __half l3 = __float2half(v.w - __half2float(h3));
    __half2 p0 = __halves2half2(h0, h1), p1 = __halves2half2(h2, h3);
    __half2 q0 = __halves2half2(l0, l1), q1 = __halves2half2(l2, l3);
    uint2 uh, ul;
    uh.x = *(unsigned*)&p0; uh.y = *(unsigned*)&p1;
    ul.x = *(unsigned*)&q0; ul.y = *(unsigned*)&q1;
    ((uint2*)g_whi)[i] = uh;
    ((uint2*)g_wlo)[i] = ul;
}

// ============================================================
// fp16-split tensor-core NT GEMM:
//   C[M,1024] = A[M,1024] @ W[1024,1024]^T (+bias)
//   D = Ahi*Whi + Ahi*Wlo + Alo*Whi  (fp32 accumulators)
// BM=BN=128, BK=32(fp16), 256 threads, warp tile 32x64, m16n8k16.
// Single-buffered smem + register prefetch (round-5 proven pattern).
// ============================================================
#define AROW 40   // 32 data + 8 pad fp16 per row; 80B row stride

__global__ __launch_bounds__(256) void gemm_fp16_split(const float* __restrict__ bias,
                                                       float* __restrict__ Cout)
{
    __shared__ __align__(16) __half tiles[4][128 * AROW];  // Ahi, Alo, Whi, Wlo
    float* C = Cout ? Cout : g_w;
    const int tid = threadIdx.x;
    const int m0 = blockIdx.y * 128, n0 = blockIdx.x * 128;
    const int lane = tid & 31, warp = tid >> 5;
    const int grp = lane >> 2, qid = lane & 3;
    const int wm0 = (warp & 3) * 32;   // 4 warps on M
    const int wn0 = (warp >> 2) * 64;  // 2 warps on N

    // loader coords: per tile 512 uint4 (16B = 8 halves); 2 per thread
    const int rowL0 = tid >> 2,        c8L0 = tid & 3;
    const int rowL1 = (tid + 256) >> 2, c8L1 = c8L0;

    float acc[2][8][4];
#pragma unroll
    for (int mi = 0; mi < 2; mi++)
#pragma unroll
        for (int n8 = 0; n8 < 8; n8++)
#pragma unroll
            for (int j = 0; j < 4; j++) acc[mi][n8][j] = 0.f;

    uint4 pf[4][2];
    // prefetch chunk 0
#pragma unroll
    for (int t = 0; t < 4; t++) {
        const __half* s = (t == 0) ? g_ahi : (t == 1) ? g_alo : (t == 2) ? g_whi : g_wlo;
        const int rb = (t < 2) ? m0 : n0;
        pf[t][0] = *(const uint4*)&s[(size_t)(rb + rowL0) * 1024 + c8L0 * 8];
        pf[t][1] = *(const uint4*)&s[(size_t)(rb + rowL1) * 1024 + c8L1 * 8];
    }

    const uint32_t sbase = smem_u32(tiles);

    for (int kc = 0; kc < 32; kc++) {
        // store prefetched chunk
#pragma unroll
        for (int t = 0; t < 4; t++) {
            *(uint4*)&tiles[t][rowL0 * AROW + c8L0 * 8] = pf[t][0];
            *(uint4*)&tiles[t][rowL1 * AROW + c8L1 * 8] = pf[t][1];
        }
        __syncthreads();

        if (kc + 1 < 32) {
            const int k0 = (kc + 1) * 32;
#pragma unroll
            for (int t = 0; t < 4; t++) {
                const __half* s = (t == 0) ? g_ahi : (t == 1) ? g_alo
                                 : (t == 2) ? g_whi : g_wlo;
                const int rb = (t < 2) ? m0 : n0;
                pf[t][0] = *(const uint4*)&s[(size_t)(rb + rowL0) * 1024 + k0 + c8L0 * 8];
                pf[t][1] = *(const uint4*)&s[(size_t)(rb + rowL1) * 1024 + k0 + c8L1 * 8];
            }
        }

#pragma unroll
        for (int ks = 0; ks < 2; ks++) {
            const int kk = ks * 16;
            uint32_t ah[2][4], al[2][4], bh[4][4], bl[4][4];
#pragma unroll
            for (int mi = 0; mi < 2; mi++) {
                // ldmatrix x4: lanes 0-15 -> rows (m), lane>>4 -> k half
                uint32_t ofs = (uint32_t)((wm0 + mi * 16 + (lane & 15)) * AROW
                                          + kk + 8 * (lane >> 4)) * 2;
                ldsm_x4(ah[mi], sbase + 0 * 10240 + ofs);
                ldsm_x4(al[mi], sbase + 1 * 10240 + ofs);
            }
#pragma unroll
            for (int nj = 0; nj < 4; nj++) {
                // matrices: (n0-7,k0) (n0-7,k8) (n8-15,k0) (n8-15,k8)
                uint32_t ofs = (uint32_t)((wn0 + nj * 16 + (lane & 7) + ((lane >> 4) << 3)) * AROW
                                          + kk + 8 * ((lane >> 3) & 1)) * 2;
                ldsm_x4(bh[nj], sbase + 2 * 10240 + ofs);
                ldsm_x4(bl[nj], sbase + 3 * 10240 + ofs);
            }
#pragma unroll
            for (int mi = 0; mi < 2; mi++)
#pragma unroll
                for (int nj = 0; nj < 4; nj++)
#pragma unroll
                    for (int h = 0; h < 2; h++) {
                        float* c = acc[mi][nj * 2 + h];
                        mma_fp16(c, ah[mi], &bh[nj][h * 2]);   // hi*hi
                        mma_fp16(c, ah[mi], &bl[nj][h * 2]);   // hi*lo
                        mma_fp16(c, al[mi], &bh[nj][h * 2]);   // lo*hi
                    }
        }
        __syncthreads();
    }

    // epilogue: c0/c1 @ (grp, 2qid/+1), c2/c3 @ (grp+8, ...)
#pragma unroll
    for (int mi = 0; mi < 2; mi++) {
        int r = m0 + wm0 + mi * 16 + grp;
#pragma unroll
        for (int n8 = 0; n8 < 8; n8++) {
            int c = n0 + wn0 + n8 * 8 + 2 * qid;
            float b0 = 0.f, b1 = 0.f;
            if (bias) { b0 = bias[c]; b1 = bias[c + 1]; }
            float* a = acc[mi][n8];
            *(float2*)&C[(size_t)r * 1024 + c]       = make_float2(a[0] + b0, a[1] + b1);
            *(float2*)&C[(size_t)(r + 8) * 1024 + c] = make_float2(a[2] + b0, a[3] + b1);
        }
    }
}

// ============================================================
// 3x3 adaptive mean pool -> rep0 (b,h,64,64)
// ============================================================
__global__ void pool_kernel()
{
    int idx = blockIdx.x * blockDim.x + threadIdx.x;
    int d  = idx & 63;
    int p  = (idx >> 6) & 63;
    int hh = (idx >> 12) & 15;
    int b  = idx >> 16;
    int py = p >> 3, px = p & 7;
    float s = 0.f;
#pragma unroll
    for (int r = 0; r < 3; r++)
#pragma unroll
        for (int c = 0; c < 3; c++) {
            int t = (3*py + r) * 24 + 3*px + c;
            s += g_w[((size_t)b * N_ + t) * DIM_ + hh * 64 + d];
        }
    g_rep[idx] = s * (1.f / 9.f);
}

// ============================================================
// attention-1 scores: S = scale * Q K^T
// ============================================================
__global__ __launch_bounds__(256) void qk_kernel()
{
    __shared__ float Qt[64][64];
    __shared__ float Kt[64][64];
    int bh = blockIdx.y;
    int b = bh >> 4, h = bh & 15;
    int t0 = blockIdx.x * 64;
    int tid = threadIdx.x, tx = tid & 15, ty = tid >> 4;

    const float* repb = g_rep + (size_t)bh * 4096;
#pragma unroll
    for (int l = 0; l < 4; l++) {
        int f = tid + l * 256;
        int q = f >> 4, dq = f & 15;
        float4 v = *(const float4*)&repb[q * 64 + dq * 4];
        Qt[dq*4+0][q] = v.x; Qt[dq*4+1][q] = v.y;
        Qt[dq*4+2][q] = v.z; Qt[dq*4+3][q] = v.w;
    }
#pragma unroll
    for (int l = 0; l < 4; l++) {
        int f = tid + l * 256;
        int t = f >> 4, dq = f & 15;
        float4 v = make_float4(0,0,0,0);
        if (t0 + t < N_)
            v = *(const float4*)&g_w[((size_t)b * N_ + t0 + t) * DIM_ + h * 64 + dq * 4];
        Kt[dq*4+0][t] = v.x; Kt[dq*4+1][t] = v.y;
        Kt[dq*4+2][t] = v.z; Kt[dq*4+3][t] = v.w;
    }
    __syncthreads();

    float acc[4][4] = {};
#pragma unroll 16
    for (int d = 0; d < 64; d++) {
        float4 qv = *(float4*)&Qt[d][4*ty];
        float4 kv = *(float4*)&Kt[d][4*tx];
        float qa[4] = {qv.x,qv.y,qv.z,qv.w};
        float ka[4] = {kv.x,kv.y,kv.z,kv.w};
#pragma unroll
        for (int i = 0; i < 4; i++)
#pragma unroll
            for (int j = 0; j < 4; j++) acc[i][j] += qa[i] * ka[j];
    }

    float* S = g_attn + (size_t)bh * 64 * N_;
    const float scale = 0.125f;
#pragma unroll
    for (int i = 0; i < 4; i++) {
        int q = 4*ty + i;
#pragma unroll
        for (int j = 0; j < 4; j++) {
            int t = t0 + 4*tx + j;
            if (t < N_) S[(size_t)q * N_ + t] = acc[i][j] * scale;
        }
    }
}

// ============================================================
// softmax over last dim (577)
// ============================================================
__global__ __launch_bounds__(256) void softmax_kernel()
{
    int bh = blockIdx.x;
    int w = threadIdx.x >> 5, lane = threadIdx.x & 31;
    for (int rr = 0; rr < 8; rr++) {
        int q = w * 8 + rr;
        float* p = g_attn + (size_t)bh * 64 * N_ + (size_t)q * N_;
        float v[19];
        float m = -INFINITY;
#pragma unroll
        for (int i = 0; i < 19; i++) {
            int idx = i * 32 + lane;
            v[i] = (idx < N_) ? p[idx] : -INFINITY;
            m = fmaxf(m, v[i]);
        }
#pragma unroll
        for (int o = 16; o > 0; o >>= 1) m = fmaxf(m, __shfl_xor_sync(0xffffffffu, m, o));
        float s = 0.f;
#pragma unroll
        for (int i = 0; i < 19; i++) { v[i] = __expf(v[i] - m); s += v[i]; }
#pragma unroll
        for (int o = 16; o > 0; o >>= 1) s += __shfl_xor_sync(0xffffffffu, s, o);
        float inv = 1.f / s;
#pragma unroll
        for (int i = 0; i < 19; i++) {
            int idx = i * 32 + lane;
            if (idx < N_) p[idx] = v[i] * inv;
        }
    }
}

// ============================================================
// rep_delta = P @ V;  rep += step_rep * rep_delta
// ============================================================
__global__ __launch_bounds__(256) void pv_kernel(const float* __restrict__ step_rep)
{
    __shared__ float Ps[64][68];
    __shared__ float Vs[64][64];
    int bh = blockIdx.x, b = bh >> 4, h = bh & 15;
    int tid = threadIdx.x, tx = tid & 15, ty = tid >> 4;
    const float* P = g_attn + (size_t)bh * 64 * N_;

    float acc[4][4] = {};
    for (int t0 = 0; t0 < N_; t0 += 64) {
        __syncthreads();
#pragma unroll
        for (int l = 0; l < 16; l++) {
            int f = tid + l * 256;
            int tl = f & 63, q = f >> 6;
            Ps[tl][q] = (t0 + tl < N_) ? P[(size_t)q * N_ + t0 + tl] : 0.f;
        }
#pragma unroll
        for (int l = 0; l < 4; l++) {
            int f = tid + l * 256;
            int t = f >> 4, dq = f & 15;
            float4 v = make_float4(0,0,0,0);
            if (t0 + t < N_)
                v = *(const float4*)&g_w[((size_t)b * N_ + t0 + t) * DIM_ + h * 64 + dq * 4];
            *(float4*)&Vs[t][dq * 4] = v;
        }
        __syncthreads();
#pragma unroll 16
        for (int t = 0; t < 64; t++) {
            float4 pv = *(float4*)&Ps[t][4*ty];
            float4 vv = *(float4*)&Vs[t][4*tx];
            float pa[4] = {pv.x,pv.y,pv.z,pv.w};
            float va[4] = {vv.x,vv.y,vv.z,vv.w};
#pragma unroll
            for (int i = 0; i < 4; i++)
#pragma unroll
                for (int j = 0; j < 4; j++) acc[i][j] += pa[i] * va[j];
        }
    }

    float step = step_rep[h];
    float* R = g_rep + (size_t)bh * 4096;
#pragma unroll
    for (int i = 0; i < 4; i++) {
        int q = 4*ty + i;
        float4 old = *(float4*)&R[q * 64 + 4*tx];
        old.x += step * acc[i][0]; old.y += step * acc[i][1];
        old.z += step * acc[i][2]; old.w += step * acc[i][3];
        *(float4*)&R[q * 64 + 4*tx] = old;
    }
}

// ============================================================
// attention-2 (self-attn of rep)
// ============================================================
__global__ __launch_bounds__(256) void attn2_kernel()
{
    __shared__ float Rt[64][64];
    __shared__ float Rn[64][64];
    __shared__ float Ss[64][64];
    int bh = blockIdx.x;
    int tid = threadIdx.x, tx = tid & 15, ty = tid >> 4;
    const float* R = g_rep + (size_t)bh * 4096;

#pragma unroll
    for (int l = 0; l < 4; l++) {
        int f = tid + l * 256;
        int q = f >> 4, dq = f & 15;
        float4 v = *(const float4*)&R[q * 64 + dq * 4];
        *(float4*)&Rn[q][dq * 4] = v;
        Rt[dq*4+0][q] = v.x; Rt[dq*4+1][q] = v.y;
        Rt[dq*4+2][q] = v.z; Rt[dq*4+3][q] = v.w;
    }
    __syncthreads();

    float acc[4][4] = {};
#pragma unroll 16
    for (int d = 0; d < 64; d++) {
        float4 qv = *(float4*)&Rt[d][4*ty];
        float4 kv = *(float4*)&Rt[d][4*tx];
        float qa[4] = {qv.x,qv.y,qv.z,qv.w};
        float ka[4] = {kv.x,kv.y,kv.z,kv.w};
#pragma unroll
        for (int i = 0; i < 4; i++)
#pragma unroll
            for (int j = 0; j < 4; j++) acc[i][j] += qa[i] * ka[j];
    }
    const float scale = 0.125f;
#pragma unroll
    for (int i = 0; i < 4; i++)
        *(float4*)&Ss[4*ty + i][4*tx] = make_float4(acc[i][0]*scale, acc[i][1]*scale,
                                                    acc[i][2]*scale, acc[i][3]*scale);
    __syncthreads();

    {
        int w = tid >> 5, lane = tid & 31;
        for (int rr = 0; rr < 8; rr++) {
            int q = w * 8 + rr;
            float v0 = Ss[q][lane], v1 = Ss[q][32 + lane];
            float m = fmaxf(v0, v1);
#pragma unroll
            for (int o = 16; o > 0; o >>= 1) m = fmaxf(m, __shfl_xor_sync(0xffffffffu, m, o));
            v0 = __expf(v0 - m); v1 = __expf(v1 - m);
            float s = v0 + v1;
#pragma unroll
            for (int o = 16; o > 0; o >>= 1) s += __shfl_xor_sync(0xffffffffu, s, o);
            float inv = 1.f / s;
            Ss[q][lane] = v0 * inv; Ss[q][32 + lane] = v1 * inv;
        }
    }
    __syncthreads();

    float acc2[4][4] = {};
#pragma unroll 16
    for (int k = 0; k < 64; k++) {
        float pv[4];
#pragma unroll
        for (int i = 0; i < 4; i++) pv[i] = Ss[4*ty + i][k];
        float4 rv = *(float4*)&Rn[k][4*tx];
        float ra[4] = {rv.x,rv.y,rv.z,rv.w};
#pragma unroll
        for (int i = 0; i < 4; i++)
#pragma unroll
            for (int j = 0; j < 4; j++) acc2[i][j] += pv[i] * ra[j];
    }
    float* O = g_out2 + (size_t)bh * 4096;
#pragma unroll
    for (int i = 0; i < 4; i++)
        *(float4*)&O[(4*ty + i) * 64 + 4*tx] = make_float4(acc2[i][0], acc2[i][1],
                                                           acc2[i][2], acc2[i][3]);
}

// ============================================================
// x_delta = step_x * (attn^T @ out2) -> g_w as (b,n,c)
// ============================================================
__global__ __launch_bounds__(256) void xdelta_kernel(const float* __restrict__ step_x)
{
    __shared__ float Ap[64][64];
    __shared__ float Os[64][64];
    int bh = blockIdx.y, b = bh >> 4, h = bh & 15;
    int t0 = blockIdx.x * 64;
    int tid = threadIdx.x, tx = tid & 15, ty = tid >> 4;
    const float* P  = g_attn + (size_t)bh * 64 * N_;
    const float* O2 = g_out2 + (size_t)bh * 4096;

#pragma unroll
    for (int l = 0; l < 16; l++) {
        int f = tid + l * 256;
        int tl = f & 63, p = f >> 6;
        Ap[p][tl] = (t0 + tl < N_) ? P[(size_t)p * N_ + t0 + tl] : 0.f;
    }
#pragma unroll
    for (int l = 0; l < 4; l++) {
        int f = tid + l * 256;
        int p = f >> 4, dq = f & 15;
        *(float4*)&Os[p][dq * 4] = *(const float4*)&O2[p * 64 + dq * 4];
    }
    __syncthreads();

    float acc[4][4] = {};
#pragma unroll 16
    for (int p = 0; p < 64; p++) {
        float4 av = *(float4*)&Ap[p][4*ty];
        float4 ov = *(float4*)&Os[p][4*tx];
        float aa[4] = {av.x,av.y,av.z,av.w};
        float oa[4] = {ov.x,ov.y,ov.z,ov.w};
#pragma unroll
        for (int i = 0; i < 4; i++)
#pragma unroll
            for (int j = 0; j < 4; j++) acc[i][j] += aa[i] * oa[j];
    }

    float step = step_x[h];
#pragma unroll
    for (int i = 0; i < 4; i++) {
        int t = t0 + 4*ty + i;
        if (t < N_) {
            float4 o = make_float4(step*acc[i][0], step*acc[i][1],
                                   step*acc[i][2], step*acc[i][3]);
            *(float4*)&g_w[((size_t)b * N_ + t) * DIM_ + h * 64 + 4*tx] = o;
        }
    }
}

// ============================================================
extern "C" void kernel_launch(void* const* d_in, const int* in_sizes, int n_in,
                              void* d_out, int out_size)
{
    (void)in_sizes; (void)n_in; (void)out_size;
    const float* x        = (const float*)d_in[0];
    const float* W_proj   = (const float*)d_in[1];
    const float* step_x   = (const float*)d_in[2];
    const float* step_rep = (const float*)d_in[3];
    const float* W_out    = (const float*)d_in[4];
    const float* b_out    = (const float*)d_in[5];
    float* out = (float*)d_out;

    dim3 gemm_grid(DIM_ / 128, M_ROWS / 128);   // (8, 577)

    split_a_kernel<<<M_ROWS * DIM_ / 1024, 256>>>(x);       // x -> ahi/alo
    split_w_kernel<<<DIM_ * DIM_ / 1024, 256>>>(W_proj);
    gemm_fp16_split<<<gemm_grid, 256>>>(nullptr, nullptr);  // -> g_w
    pool_kernel<<<(BH_ * 64 * 64) / 256, 256>>>();
    qk_kernel<<<dim3(10, BH_), 256>>>();
    softmax_kernel<<<BH_, 256>>>();
    pv_kernel<<<BH_, 256>>>(step_rep);
    attn2_kernel<<<BH_, 256>>>();
    xdelta_kernel<<<dim3(10, BH_), 256>>>(step_x);
    split_a_kernel<<<M_ROWS * DIM_ / 1024, 256>>>(nullptr); // g_w(x_delta) -> ahi/alo
    split_w_kernel<<<DIM_ * DIM_ / 1024, 256>>>(W_out);
    gemm_fp16_split<<<gemm_grid, 256>>>(b_out, out);
}

// round 15
// speedup vs baseline: 2.3843x; 1.4847x over previous
#include <cuda_runtime.h>
#include <cuda_fp16.h>
#include <stdint.h>

#define B_   128
#define N_   577
#define DIM_ 1024
#define H_   16
#define BH_  (B_*H_)
#define M_ROWS (B_*N_)   // 73856

// ---- scratch (static device allocations; no cudaMalloc anywhere) ----
static __device__ float g_w[(size_t)M_ROWS*DIM_];      // w = x@Wp^T
static __device__ float g_attn[(size_t)BH_*64*N_];     // attention-1 probs
static __device__ float g_rep[(size_t)BH_*64*64];      // rep
static __device__ float g_out2[(size_t)BH_*64*64];     // attention-2 output
static __device__ __half g_ahi[(size_t)M_ROWS*DIM_];   // fp16 A operand (x, later x_delta)
static __device__ __half g_whi[(size_t)DIM_*DIM_];     // fp16 hi of weight
static __device__ __half g_wlo[(size_t)DIM_*DIM_];     // fp16 lo residual of weight

// ============================================================
// warp-MMA helpers (sm_103-legal: ldmatrix + mma.sync fp16) — R14-proven
// ============================================================
__device__ __forceinline__ uint32_t smem_u32(const void* p) {
    return (uint32_t)__cvta_generic_to_shared(p);
}
__device__ __forceinline__ void ldsm_x4(uint32_t* r, uint32_t addr) {
    asm volatile("ldmatrix.sync.aligned.m8n8.x4.shared.b16 {%0,%1,%2,%3}, [%4];"
                 : "=r"(r[0]), "=r"(r[1]), "=r"(r[2]), "=r"(r[3]) : "r"(addr));
}
__device__ __forceinline__ void mma_fp16(float* c, const uint32_t* a, const uint32_t* b) {
    asm volatile("mma.sync.aligned.m16n8k16.row.col.f32.f16.f16.f32 "
                 "{%0,%1,%2,%3}, {%4,%5,%6,%7}, {%8,%9}, {%0,%1,%2,%3};"
                 : "+f"(c[0]), "+f"(c[1]), "+f"(c[2]), "+f"(c[3])
                 : "r"(a[0]), "r"(a[1]), "r"(a[2]), "r"(a[3]),
                   "r"(b[0]), "r"(b[1]));
}
#define CP16(dst, src) \
    asm volatile("cp.async.ca.shared.global [%0], [%1], 16;" :: "r"(dst), "l"(src) : "memory")
#define CP_COMMIT() asm volatile("cp.async.commit_group;" ::: "memory")

// ============================================================
// splits
// ============================================================
__global__ __launch_bounds__(256) void split_a_hi(const float* __restrict__ src)
{
    size_t i = (size_t)blockIdx.x * 256 + threadIdx.x;   // one float4 each
    float4 v = ((const float4*)src)[i];
    __half2 p0 = __halves2half2(__float2half(v.x), __float2half(v.y));
    __half2 p1 = __halves2half2(__float2half(v.z), __float2half(v.w));
    uint2 u; u.x = *(unsigned*)&p0; u.y = *(unsigned*)&p1;
    ((uint2*)g_ahi)[i] = u;
}

__global__ __launch_bounds__(256) void split_w_kernel(const float* __restrict__ src)
{
    size_t i = (size_t)blockIdx.x * 256 + threadIdx.x;
    float4 v = ((const float4*)src)[i];
    __half h0 = __float2half(v.x), h1 = __float2half(v.y);
    __half h2 = __float2half(v.z), h3 = __float2half(v.w);
    __half l0 = __float2half(v.x - __half2float(h0));
    __half l1 = __float2half(v.y - __half2float(h1));
    __half l2 = __float2half(v.z - __half2float(h2));
    __half l3 = __float2half(v.w - __half2float(h3));
    __half2 p0 = __halves2half2(h0, h1), p1 = __halves2half2(h2, h3);
    __half2 q0 = __halves2half2(l0, l1), q1 = __halves2half2(l2, l3);
    uint2 uh, ul;
    uh.x = *(unsigned*)&p0; uh.y = *(unsigned*)&p1;
    ul.x = *(unsigned*)&q0; ul.y = *(unsigned*)&q1;
    ((uint2*)g_whi)[i] = uh;
    ((uint2*)g_wlo)[i] = ul;
}

// ============================================================
// fp16 tensor-core NT GEMM:  C[M,1024] = Ahi @ (Whi+Wlo)^T (+bias)
// BM=BN=128, BK=32, 256 threads, warp tile 32x64, m16n8k16.
// cp.async 2-stage pipeline, 3 tiles/stage (Ahi, Whi, Wlo).
// ============================================================
#define AROW 40            // 32 data + 8 pad halves/row; 80B stride (conflict-free)
#define TILE_B (128*AROW*2)  // 10240 bytes per tile
#define GEMM_SMEM (2*3*TILE_B)  // 61440

__global__ __launch_bounds__(256, 2) void gemm_fp16_split(const float* __restrict__ bias,
                                                          float* __restrict__ Cout)
{
    extern __shared__ __align__(16) __half sm[];
    float* C = Cout ? Cout : g_w;
    const int tid = threadIdx.x;
    const int m0 = blockIdx.y * 128, n0 = blockIdx.x * 128;
    const int lane = tid & 31, warp = tid >> 5;
    const int grp = lane >> 2, qid = lane & 3;
    const int wm0 = (warp & 3) * 32;   // 4 warps on M
    const int wn0 = (warp >> 2) * 64;  // 2 warps on N
    const uint32_t sbase = smem_u32(sm);

    // loader coords: per tile 2 x 16B per thread
    const int rowL0 = tid >> 2, rowL1 = rowL0 + 64;
    const int c8 = (tid & 3) * 8;

    float acc[2][8][4];
#pragma unroll
    for (int mi = 0; mi < 2; mi++)
#pragma unroll
        for (int n8 = 0; n8 < 8; n8++)
#pragma unroll
            for (int j = 0; j < 4; j++) acc[mi][n8][j] = 0.f;

    // stage issue: 3 tiles (0=Ahi@m0, 1=Whi@n0, 2=Wlo@n0), K-chunk kc
#define ISSUE_STAGE(s, kc) do {                                                   \
        const int kcol = (kc) * 32;                                               \
        const uint32_t st = sbase + (s) * (3 * TILE_B);                           \
        CP16(st + 0*TILE_B + (rowL0*AROW + c8)*2,                                 \
             &g_ahi[(size_t)(m0 + rowL0) * 1024 + kcol + c8]);                    \
        CP16(st + 0*TILE_B + (rowL1*AROW + c8)*2,                                 \
             &g_ahi[(size_t)(m0 + rowL1) * 1024 + kcol + c8]);                    \
        CP16(st + 1*TILE_B + (rowL0*AROW + c8)*2,                                 \
             &g_whi[(size_t)(n0 + rowL0) * 1024 + kcol + c8]);                    \
        CP16(st + 1*TILE_B + (rowL1*AROW + c8)*2,                                 \
             &g_whi[(size_t)(n0 + rowL1) * 1024 + kcol + c8]);                    \
        CP16(st + 2*TILE_B + (rowL0*AROW + c8)*2,                                 \
             &g_wlo[(size_t)(n0 + rowL0) * 1024 + kcol + c8]);                    \
        CP16(st + 2*TILE_B + (rowL1*AROW + c8)*2,                                 \
             &g_wlo[(size_t)(n0 + rowL1) * 1024 + kcol + c8]);                    \
        CP_COMMIT();                                                              \
    } while (0)

    ISSUE_STAGE(0, 0);
    ISSUE_STAGE(1, 1);

    for (int kc = 0; kc < 32; kc++) {
        const int s = kc & 1;
        if (kc < 31) asm volatile("cp.async.wait_group 1;" ::: "memory");
        else         asm volatile("cp.async.wait_group 0;" ::: "memory");
        __syncthreads();

        const uint32_t stA = sbase + s * (3 * TILE_B);
        const uint32_t stBh = stA + TILE_B, stBl = stA + 2 * TILE_B;
#pragma unroll
        for (int ks = 0; ks < 2; ks++) {
            const int kk = ks * 16;
            uint32_t ah[2][4], bh[4][4], bl[4][4];
#pragma unroll
            for (int mi = 0; mi < 2; mi++) {
                uint32_t ofs = (uint32_t)((wm0 + mi * 16 + (lane & 15)) * AROW
                                          + kk + 8 * (lane >> 4)) * 2;
                ldsm_x4(ah[mi], stA + ofs);
            }
#pragma unroll
            for (int nj = 0; nj < 4; nj++) {
                uint32_t ofs = (uint32_t)((wn0 + nj * 16 + (lane & 7) + ((lane >> 4) << 3)) * AROW
                                          + kk + 8 * ((lane >> 3) & 1)) * 2;
                ldsm_x4(bh[nj], stBh + ofs);
                ldsm_x4(bl[nj], stBl + ofs);
            }
#pragma unroll
            for (int mi = 0; mi < 2; mi++)
#pragma unroll
                for (int nj = 0; nj < 4; nj++)
#pragma unroll
                    for (int h = 0; h < 2; h++) {
                        float* c = acc[mi][nj * 2 + h];
                        mma_fp16(c, ah[mi], &bh[nj][h * 2]);   // hi*hi
                        mma_fp16(c, ah[mi], &bl[nj][h * 2]);   // hi*lo (W residual)
                    }
        }
        __syncthreads();
        if (kc + 2 < 32) ISSUE_STAGE(s, kc + 2);
    }
#undef ISSUE_STAGE

    // epilogue: c0/c1 @ (grp, 2qid/+1), c2/c3 @ (grp+8, ...)
#pragma unroll
    for (int mi = 0; mi < 2; mi++) {
        int r = m0 + wm0 + mi * 16 + grp;
#pragma unroll
        for (int n8 = 0; n8 < 8; n8++) {
            int c = n0 + wn0 + n8 * 8 + 2 * qid;
            float b0 = 0.f, b1 = 0.f;
            if (bias) { b0 = bias[c]; b1 = bias[c + 1]; }
            float* a = acc[mi][n8];
            *(float2*)&C[(size_t)r * 1024 + c]       = make_float2(a[0] + b0, a[1] + b1);
            *(float2*)&C[(size_t)(r + 8) * 1024 + c] = make_float2(a[2] + b0, a[3] + b1);
        }
    }
}

// ============================================================
// 3x3 adaptive mean pool -> rep0 (b,h,64,64)
// ============================================================
__global__ void pool_kernel()
{
    int idx = blockIdx.x * blockDim.x + threadIdx.x;
    int d  = idx & 63;
    int p  = (idx >> 6) & 63;
    int hh = (idx >> 12) & 15;
    int b  = idx >> 16;
    int py = p >> 3, px = p & 7;
    float s = 0.f;
#pragma unroll
    for (int r = 0; r < 3; r++)
#pragma unroll
        for (int c = 0; c < 3; c++) {
            int t = (3*py + r) * 24 + 3*px + c;
            s += g_w[((size_t)b * N_ + t) * DIM_ + hh * 64 + d];
        }
    g_rep[idx] = s * (1.f / 9.f);
}

// ============================================================
// attention-1 scores: S = scale * Q K^T
// ============================================================
__global__ __launch_bounds__(256) void qk_kernel()
{
    __shared__ float Qt[64][64];
    __shared__ float Kt[64][64];
    int bh = blockIdx.y;
    int b = bh >> 4, h = bh & 15;
    int t0 = blockIdx.x * 64;
    int tid = threadIdx.x, tx = tid & 15, ty = tid >> 4;

    const float* repb = g_rep + (size_t)bh * 4096;
#pragma unroll
    for (int l = 0; l < 4; l++) {
        int f = tid + l * 256;
        int q = f >> 4, dq = f & 15;
        float4 v = *(const float4*)&repb[q * 64 + dq * 4];
        Qt[dq*4+0][q] = v.x; Qt[dq*4+1][q] = v.y;
        Qt[dq*4+2][q] = v.z; Qt[dq*4+3][q] = v.w;
    }
#pragma unroll
    for (int l = 0; l < 4; l++) {
        int f = tid + l * 256;
        int t = f >> 4, dq = f & 15;
        float4 v = make_float4(0,0,0,0);
        if (t0 + t < N_)
            v = *(const float4*)&g_w[((size_t)b * N_ + t0 + t) * DIM_ + h * 64 + dq * 4];
        Kt[dq*4+0][t] = v.x; Kt[dq*4+1][t] = v.y;
        Kt[dq*4+2][t] = v.z; Kt[dq*4+3][t] = v.w;
    }
    __syncthreads();

    float acc[4][4] = {};
#pragma unroll 16
    for (int d = 0; d < 64; d++) {
        float4 qv = *(float4*)&Qt[d][4*ty];
        float4 kv = *(float4*)&Kt[d][4*tx];
        float qa[4] = {qv.x,qv.y,qv.z,qv.w};
        float ka[4] = {kv.x,kv.y,kv.z,kv.w};
#pragma unroll
        for (int i = 0; i < 4; i++)
#pragma unroll
            for (int j = 0; j < 4; j++) acc[i][j] += qa[i] * ka[j];
    }

    float* S = g_attn + (size_t)bh * 64 * N_;
    const float scale = 0.125f;
#pragma unroll
    for (int i = 0; i < 4; i++) {
        int q = 4*ty + i;
#pragma unroll
        for (int j = 0; j < 4; j++) {
            int t = t0 + 4*tx + j;
            if (t < N_) S[(size_t)q * N_ + t] = acc[i][j] * scale;
        }
    }
}

// ============================================================
// softmax over last dim (577)
// ============================================================
__global__ __launch_bounds__(256) void softmax_kernel()
{
    int bh = blockIdx.x;
    int w = threadIdx.x >> 5, lane = threadIdx.x & 31;
    for (int rr = 0; rr < 8; rr++) {
        int q = w * 8 + rr;
        float* p = g_attn + (size_t)bh * 64 * N_ + (size_t)q * N_;
        float v[19];
        float m = -INFINITY;
#pragma unroll
        for (int i = 0; i < 19; i++) {
            int idx = i * 32 + lane;
            v[i] = (idx < N_) ? p[idx] : -INFINITY;
            m = fmaxf(m, v[i]);
        }
#pragma unroll
        for (int o = 16; o > 0; o >>= 1) m = fmaxf(m, __shfl_xor_sync(0xffffffffu, m, o));
        float s = 0.f;
#pragma unroll
        for (int i = 0; i < 19; i++) { v[i] = __expf(v[i] - m); s += v[i]; }
#pragma unroll
        for (int o = 16; o > 0; o >>= 1) s += __shfl_xor_sync(0xffffffffu, s, o);
        float inv = 1.f / s;
#pragma unroll
        for (int i = 0; i < 19; i++) {
            int idx = i * 32 + lane;
            if (idx < N_) p[idx] = v[i] * inv;
        }
    }
}

// ============================================================
// rep_delta = P @ V;  rep += step_rep * rep_delta
// ============================================================
__global__ __launch_bounds__(256) void pv_kernel(const float* __restrict__ step_rep)
{
    __shared__ float Ps[64][68];
    __shared__ float Vs[64][64];
    int bh = blockIdx.x, b = bh >> 4, h = bh & 15;
    int tid = threadIdx.x, tx = tid & 15, ty = tid >> 4;
    const float* P = g_attn + (size_t)bh * 64 * N_;

    float acc[4][4] = {};
    for (int t0 = 0; t0 < N_; t0 += 64) {
        __syncthreads();
#pragma unroll
        for (int l = 0; l < 16; l++) {
            int f = tid + l * 256;
            int tl = f & 63, q = f >> 6;
            Ps[tl][q] = (t0 + tl < N_) ? P[(size_t)q * N_ + t0 + tl] : 0.f;
        }
#pragma unroll
        for (int l = 0; l < 4; l++) {
            int f = tid + l * 256;
            int t = f >> 4, dq = f & 15;
            float4 v = make_float4(0,0,0,0);
            if (t0 + t < N_)
                v = *(const float4*)&g_w[((size_t)b * N_ + t0 + t) * DIM_ + h * 64 + dq * 4];
            *(float4*)&Vs[t][dq * 4] = v;
        }
        __syncthreads();
#pragma unroll 16
        for (int t = 0; t < 64; t++) {
            float4 pv = *(float4*)&Ps[t][4*ty];
            float4 vv = *(float4*)&Vs[t][4*tx];
            float pa[4] = {pv.x,pv.y,pv.z,pv.w};
            float va[4] = {vv.x,vv.y,vv.z,vv.w};
#pragma unroll
            for (int i = 0; i < 4; i++)
#pragma unroll
                for (int j = 0; j < 4; j++) acc[i][j] += pa[i] * va[j];
        }
    }

    float step = step_rep[h];
    float* R = g_rep + (size_t)bh * 4096;
#pragma unroll
    for (int i = 0; i < 4; i++) {
        int q = 4*ty + i;
        float4 old = *(float4*)&R[q * 64 + 4*tx];
        old.x += step * acc[i][0]; old.y += step * acc[i][1];
        old.z += step * acc[i][2]; old.w += step * acc[i][3];
        *(float4*)&R[q * 64 + 4*tx] = old;
    }
}

// ============================================================
// attention-2 (self-attn of rep)
// ============================================================
__global__ __launch_bounds__(256) void attn2_kernel()
{
    __shared__ float Rt[64][64];
    __shared__ float Rn[64][64];
    __shared__ float Ss[64][64];
    int bh = blockIdx.x;
    int tid = threadIdx.x, tx = tid & 15, ty = tid >> 4;
    const float* R = g_rep + (size_t)bh * 4096;

#pragma unroll
    for (int l = 0; l < 4; l++) {
        int f = tid + l * 256;
        int q = f >> 4, dq = f & 15;
        float4 v = *(const float4*)&R[q * 64 + dq * 4];
        *(float4*)&Rn[q][dq * 4] = v;
        Rt[dq*4+0][q] = v.x; Rt[dq*4+1][q] = v.y;
        Rt[dq*4+2][q] = v.z; Rt[dq*4+3][q] = v.w;
    }
    __syncthreads();

    float acc[4][4] = {};
#pragma unroll 16
    for (int d = 0; d < 64; d++) {
        float4 qv = *(float4*)&Rt[d][4*ty];
        float4 kv = *(float4*)&Rt[d][4*tx];
        float qa[4] = {qv.x,qv.y,qv.z,qv.w};
        float ka[4] = {kv.x,kv.y,kv.z,kv.w};
#pragma unroll
        for (int i = 0; i < 4; i++)
#pragma unroll
            for (int j = 0; j < 4; j++) acc[i][j] += qa[i] * ka[j];
    }
    const float scale = 0.125f;
#pragma unroll
    for (int i = 0; i < 4; i++)
        *(float4*)&Ss[4*ty + i][4*tx] = make_float4(acc[i][0]*scale, acc[i][1]*scale,
                                                    acc[i][2]*scale, acc[i][3]*scale);
    __syncthreads();

    {
        int w = tid >> 5, lane = tid & 31;
        for (int rr = 0; rr < 8; rr++) {
            int q = w * 8 + rr;
            float v0 = Ss[q][lane], v1 = Ss[q][32 + lane];
            float m = fmaxf(v0, v1);
#pragma unroll
            for (int o = 16; o > 0; o >>= 1) m = fmaxf(m, __shfl_xor_sync(0xffffffffu, m, o));
            v0 = __expf(v0 - m); v1 = __expf(v1 - m);
            float s = v0 + v1;
#pragma unroll
            for (int o = 16; o > 0; o >>= 1) s += __shfl_xor_sync(0xffffffffu, s, o);
            float inv = 1.f / s;
            Ss[q][lane] = v0 * inv; Ss[q][32 + lane] = v1 * inv;
        }
    }
    __syncthreads();

    float acc2[4][4] = {};
#pragma unroll 16
    for (int k = 0; k < 64; k++) {
        float pv[4];
#pragma unroll
        for (int i = 0; i < 4; i++) pv[i] = Ss[4*ty + i][k];
        float4 rv = *(float4*)&Rn[k][4*tx];
        float ra[4] = {rv.x,rv.y,rv.z,rv.w};
#pragma unroll
        for (int i = 0; i < 4; i++)
#pragma unroll
            for (int j = 0; j < 4; j++) acc2[i][j] += pv[i] * ra[j];
    }
    float* O = g_out2 + (size_t)bh * 4096;
#pragma unroll
    for (int i = 0; i < 4; i++)
        *(float4*)&O[(4*ty + i) * 64 + 4*tx] = make_float4(acc2[i][0], acc2[i][1],
                                                           acc2[i][2], acc2[i][3]);
}

// ============================================================
// x_delta = step_x * (attn^T @ out2) -> written DIRECTLY as fp16 into g_ahi
// (feeds GEMM2; the standalone second split pass is eliminated)
// ============================================================
__global__ __launch_bounds__(256) void xdelta_kernel(const float* __restrict__ step_x)
{
    __shared__ float Ap[64][64];
    __shared__ float Os[64][64];
    int bh = blockIdx.y, b = bh >> 4, h = bh & 15;
    int t0 = blockIdx.x * 64;
    int tid = threadIdx.x, tx = tid & 15, ty = tid >> 4;
    const float* P  = g_attn + (size_t)bh * 64 * N_;
    const float* O2 = g_out2 + (size_t)bh * 4096;

#pragma unroll
    for (int l = 0; l < 16; l++) {
        int f = tid + l * 256;
        int tl = f & 63, p = f >> 6;
        Ap[p][tl] = (t0 + tl < N_) ? P[(size_t)p * N_ + t0 + tl] : 0.f;
    }
#pragma unroll
    for (int l = 0; l < 4; l++) {
        int f = tid + l * 256;
        int p = f >> 4, dq = f & 15;
        *(float4*)&Os[p][dq * 4] = *(const float4*)&O2[p * 64 + dq * 4];
    }
    __syncthreads();

    float acc[4][4] = {};
#pragma unroll 16
    for (int p = 0; p < 64; p++) {
        float4 av = *(float4*)&Ap[p][4*ty];
        float4 ov = *(float4*)&Os[p][4*tx];
        float aa[4] = {av.x,av.y,av.z,av.w};
        float oa[4] = {ov.x,ov.y,ov.z,ov.w};
#pragma unroll
        for (int i = 0; i < 4; i++)
#pragma unroll
            for (int j = 0; j < 4; j++) acc[i][j] += aa[i] * oa[j];
    }

    float step = step_x[h];
#pragma unroll
    for (int i = 0; i < 4; i++) {
        int t = t0 + 4*ty + i;
        if (t < N_) {
            __half2 h0 = __halves2half2(__float2half(step*acc[i][0]),
                                        __float2half(step*acc[i][1]));
            __half2 h1 = __halves2half2(__float2half(step*acc[i][2]),
                                        __float2half(step*acc[i][3]));
            uint2 u; u.x = *(unsigned*)&h0; u.y = *(unsigned*)&h1;
            *(uint2*)&g_ahi[((size_t)b * N_ + t) * DIM_ + h * 64 + 4*tx] = u;
        }
    }
}

// ============================================================
extern "C" void kernel_launch(void* const* d_in, const int* in_sizes, int n_in,
                              void* d_out, int out_size)
{
    (void)in_sizes; (void)n_in; (void)out_size;
    const float* x        = (const float*)d_in[0];
    const float* W_proj   = (const float*)d_in[1];
    const float* step_x   = (const float*)d_in[2];
    const float* step_rep = (const float*)d_in[3];
    const float* W_out    = (const float*)d_in[4];
    const float* b_out    = (const float*)d_in[5];
    float* out = (float*)d_out;

    cudaFuncSetAttribute(gemm_fp16_split,
                         cudaFuncAttributeMaxDynamicSharedMemorySize, GEMM_SMEM);

    dim3 gemm_grid(DIM_ / 128, M_ROWS / 128);   // (8, 577)

    split_a_hi<<<M_ROWS * DIM_ / 1024, 256>>>(x);           // x -> g_ahi (fp16)
    split_w_kernel<<<DIM_ * DIM_ / 1024, 256>>>(W_proj);    // -> whi/wlo
    gemm_fp16_split<<<gemm_grid, 256, GEMM_SMEM>>>(nullptr, nullptr);  // -> g_w
    pool_kernel<<<(BH_ * 64 * 64) / 256, 256>>>();
    qk_kernel<<<dim3(10, BH_), 256>>>();
    softmax_kernel<<<BH_, 256>>>();
    pv_kernel<<<BH_, 256>>>(step_rep);
    attn2_kernel<<<BH_, 256>>>();
    xdelta_kernel<<<dim3(10, BH_), 256>>>(step_x);          // -> g_ahi (fp16, fused split)
    split_w_kernel<<<DIM_ * DIM_ / 1024, 256>>>(W_out);
    gemm_fp16_split<<<gemm_grid, 256, GEMM_SMEM>>>(b_out, out);
}

// round 16
// speedup vs baseline: 2.3973x; 1.0055x over previous
#include <cuda_runtime.h>
#include <cuda_fp16.h>
#include <stdint.h>

#define B_   128
#define N_   577
#define DIM_ 1024
#define H_   16
#define BH_  (B_*H_)
#define M_ROWS (B_*N_)   // 73856

// ---- scratch (static device allocations; no cudaMalloc anywhere) ----
static __device__ float g_w[(size_t)M_ROWS*DIM_];      // w = x@Wp^T
static __device__ float g_attn[(size_t)BH_*64*N_];     // attention-1 probs
static __device__ float g_rep[(size_t)BH_*64*64];      // rep
static __device__ float g_out2[(size_t)BH_*64*64];     // attention-2 output
static __device__ __half g_ahi[(size_t)M_ROWS*DIM_];   // fp16 A operand (x, later x_delta)
static __device__ __half g_whi[(size_t)DIM_*DIM_];     // fp16 hi of weight
static __device__ __half g_wlo[(size_t)DIM_*DIM_];     // fp16 lo residual of weight

// ============================================================
// warp-MMA helpers (sm_103-legal: ldmatrix + mma.sync fp16) — R14/15-proven
// ============================================================
__device__ __forceinline__ uint32_t smem_u32(const void* p) {
    return (uint32_t)__cvta_generic_to_shared(p);
}
__device__ __forceinline__ void ldsm_x4(uint32_t* r, uint32_t addr) {
    asm volatile("ldmatrix.sync.aligned.m8n8.x4.shared.b16 {%0,%1,%2,%3}, [%4];"
                 : "=r"(r[0]), "=r"(r[1]), "=r"(r[2]), "=r"(r[3]) : "r"(addr));
}
__device__ __forceinline__ void mma_fp16(float* c, const uint32_t* a, const uint32_t* b) {
    asm volatile("mma.sync.aligned.m16n8k16.row.col.f32.f16.f16.f32 "
                 "{%0,%1,%2,%3}, {%4,%5,%6,%7}, {%8,%9}, {%0,%1,%2,%3};"
                 : "+f"(c[0]), "+f"(c[1]), "+f"(c[2]), "+f"(c[3])
                 : "r"(a[0]), "r"(a[1]), "r"(a[2]), "r"(a[3]),
                   "r"(b[0]), "r"(b[1]));
}
#define CP16(dst, src) \
    asm volatile("cp.async.ca.shared.global [%0], [%1], 16;" :: "r"(dst), "l"(src) : "memory")
#define CP_COMMIT() asm volatile("cp.async.commit_group;" ::: "memory")

// ============================================================
// splits
// ============================================================
__global__ __launch_bounds__(256) void split_a_hi(const float* __restrict__ src)
{
    size_t i = (size_t)blockIdx.x * 256 + threadIdx.x;   // one float4 each
    float4 v = ((const float4*)src)[i];
    __half2 p0 = __halves2half2(__float2half(v.x), __float2half(v.y));
    __half2 p1 = __halves2half2(__float2half(v.z), __float2half(v.w));
    uint2 u; u.x = *(unsigned*)&p0; u.y = *(unsigned*)&p1;
    ((uint2*)g_ahi)[i] = u;
}

__global__ __launch_bounds__(256) void split_w_kernel(const float* __restrict__ src)
{
    size_t i = (size_t)blockIdx.x * 256 + threadIdx.x;
    float4 v = ((const float4*)src)[i];
    __half h0 = __float2half(v.x), h1 = __float2half(v.y);
    __half h2 = __float2half(v.z), h3 = __float2half(v.w);
    __half l0 = __float2half(v.x - __half2float(h0));
    __half l1 = __float2half(v.y - __half2float(h1));
    __half l2 = __float2half(v.z - __half2float(h2));
    __half l3 = __float2half(v.w - __half2float(h3));
    __half2 p0 = __halves2half2(h0, h1), p1 = __halves2half2(h2, h3);
    __half2 q0 = __halves2half2(l0, l1), q1 = __halves2half2(l2, l3);
    uint2 uh, ul;
    uh.x = *(unsigned*)&p0; uh.y = *(unsigned*)&p1;
    ul.x = *(unsigned*)&q0; ul.y = *(unsigned*)&q1;
    ((uint2*)g_whi)[i] = uh;
    ((uint2*)g_wlo)[i] = ul;
}

// ============================================================
// fp16 tensor-core NT GEMM:  C[M,1024] = Ahi @ (Whi+Wlo)^T (+bias)
// BM=BN=128, BK=32, 128 threads, warp tile 64x64 (4 warps), m16n8k16.
// cp.async 3-stage pipeline, 3 tiles/stage (Ahi, Whi, Wlo).
// ============================================================
#define AROW 40                // 32 data + 8 pad halves/row; 80B stride (conflict-free)
#define TILE_B (128*AROW*2)    // 10240 bytes per tile
#define STAGE_B (3*TILE_B)     // 30720 per stage
#define GEMM_SMEM (3*STAGE_B)  // 92160

__global__ __launch_bounds__(128, 2) void gemm_fp16_split(const float* __restrict__ bias,
                                                          float* __restrict__ Cout)
{
    extern __shared__ __align__(16) __half sm[];
    float* C = Cout ? Cout : g_w;
    const int tid = threadIdx.x;
    const int m0 = blockIdx.y * 128, n0 = blockIdx.x * 128;
    const int lane = tid & 31, warp = tid >> 5;
    const int grp = lane >> 2, qid = lane & 3;
    const int wm0 = (warp >> 1) * 64;   // 2 warps on M
    const int wn0 = (warp & 1) * 64;    // 2 warps on N
    const uint32_t sbase = smem_u32(sm);

    float acc[4][8][4];
#pragma unroll
    for (int mi = 0; mi < 4; mi++)
#pragma unroll
        for (int n8 = 0; n8 < 8; n8++)
#pragma unroll
            for (int j = 0; j < 4; j++) acc[mi][n8][j] = 0.f;

    // stage issue: per tile 512 x 16B chunks; 128 threads x 4 chunks each
#define ISSUE_STAGE(s, kc) do {                                                   \
        const int kcol = (kc) * 32;                                               \
        const uint32_t st = sbase + (s) * STAGE_B;                                \
        _Pragma("unroll")                                                         \
        for (int i = 0; i < 4; i++) {                                             \
            int ch = i * 128 + tid;                                               \
            int row = ch >> 2, c16 = (ch & 3) * 8;                                \
            uint32_t so = (uint32_t)(row * AROW + c16) * 2;                       \
            CP16(st + 0*TILE_B + so, &g_ahi[(size_t)(m0 + row) * 1024 + kcol + c16]); \
            CP16(st + 1*TILE_B + so, &g_whi[(size_t)(n0 + row) * 1024 + kcol + c16]); \
            CP16(st + 2*TILE_B + so, &g_wlo[(size_t)(n0 + row) * 1024 + kcol + c16]); \
        }                                                                         \
        CP_COMMIT();                                                              \
    } while (0)

    ISSUE_STAGE(0, 0);
    ISSUE_STAGE(1, 1);
    ISSUE_STAGE(2, 2);

    int s = 0;
    for (int kc = 0; kc < 32; kc++) {
        if (kc < 30)       asm volatile("cp.async.wait_group 2;" ::: "memory");
        else if (kc == 30) asm volatile("cp.async.wait_group 1;" ::: "memory");
        else               asm volatile("cp.async.wait_group 0;" ::: "memory");
        __syncthreads();

        const uint32_t stA = sbase + s * STAGE_B;
        const uint32_t stBh = stA + TILE_B, stBl = stA + 2 * TILE_B;
#pragma unroll
        for (int ks = 0; ks < 2; ks++) {
            const int kk = ks * 16;
            uint32_t ah[4][4], bh4[4][4], bl4[4][4];
#pragma unroll
            for (int mi = 0; mi < 4; mi++) {
                uint32_t ofs = (uint32_t)((wm0 + mi * 16 + (lane & 15)) * AROW
                                          + kk + 8 * (lane >> 4)) * 2;
                ldsm_x4(ah[mi], stA + ofs);
            }
#pragma unroll
            for (int nj = 0; nj < 4; nj++) {
                uint32_t ofs = (uint32_t)((wn0 + nj * 16 + (lane & 7) + ((lane >> 4) << 3)) * AROW
                                          + kk + 8 * ((lane >> 3) & 1)) * 2;
                ldsm_x4(bh4[nj], stBh + ofs);
                ldsm_x4(bl4[nj], stBl + ofs);
            }
#pragma unroll
            for (int mi = 0; mi < 4; mi++)
#pragma unroll
                for (int nj = 0; nj < 4; nj++)
#pragma unroll
                    for (int h = 0; h < 2; h++) {
                        float* c = acc[mi][nj * 2 + h];
                        mma_fp16(c, ah[mi], &bh4[nj][h * 2]);   // hi*hi
                        mma_fp16(c, ah[mi], &bl4[nj][h * 2]);   // hi*lo (W residual)
                    }
        }
        __syncthreads();
        if (kc + 3 < 32) ISSUE_STAGE(s, kc + 3);
        s = (s == 2) ? 0 : s + 1;
    }
#undef ISSUE_STAGE

    // epilogue: c0/c1 @ (grp, 2qid/+1), c2/c3 @ (grp+8, ...)
#pragma unroll
    for (int mi = 0; mi < 4; mi++) {
        int r = m0 + wm0 + mi * 16 + grp;
#pragma unroll
        for (int n8 = 0; n8 < 8; n8++) {
            int c = n0 + wn0 + n8 * 8 + 2 * qid;
            float b0 = 0.f, b1 = 0.f;
            if (bias) { b0 = bias[c]; b1 = bias[c + 1]; }
            float* a = acc[mi][n8];
            *(float2*)&C[(size_t)r * 1024 + c]       = make_float2(a[0] + b0, a[1] + b1);
            *(float2*)&C[(size_t)(r + 8) * 1024 + c] = make_float2(a[2] + b0, a[3] + b1);
        }
    }
}

// ============================================================
// 3x3 adaptive mean pool -> rep0 (b,h,64,64)
// ============================================================
__global__ void pool_kernel()
{
    int idx = blockIdx.x * blockDim.x + threadIdx.x;
    int d  = idx & 63;
    int p  = (idx >> 6) & 63;
    int hh = (idx >> 12) & 15;
    int b  = idx >> 16;
    int py = p >> 3, px = p & 7;
    float s = 0.f;
#pragma unroll
    for (int r = 0; r < 3; r++)
#pragma unroll
        for (int c = 0; c < 3; c++) {
            int t = (3*py + r) * 24 + 3*px + c;
            s += g_w[((size_t)b * N_ + t) * DIM_ + hh * 64 + d];
        }
    g_rep[idx] = s * (1.f / 9.f);
}

// ============================================================
// attention-1 scores: S = scale * Q K^T
// ============================================================
__global__ __launch_bounds__(256) void qk_kernel()
{
    __shared__ float Qt[64][64];
    __shared__ float Kt[64][64];
    int bh = blockIdx.y;
    int b = bh >> 4, h = bh & 15;
    int t0 = blockIdx.x * 64;
    int tid = threadIdx.x, tx = tid & 15, ty = tid >> 4;

    const float* repb = g_rep + (size_t)bh * 4096;
#pragma unroll
    for (int l = 0; l < 4; l++) {
        int f = tid + l * 256;
        int q = f >> 4, dq = f & 15;
        float4 v = *(const float4*)&repb[q * 64 + dq * 4];
        Qt[dq*4+0][q] = v.x; Qt[dq*4+1][q] = v.y;
        Qt[dq*4+2][q] = v.z; Qt[dq*4+3][q] = v.w;
    }
#pragma unroll
    for (int l = 0; l < 4; l++) {
        int f = tid + l * 256;
        int t = f >> 4, dq = f & 15;
        float4 v = make_float4(0,0,0,0);
        if (t0 + t < N_)
            v = *(const float4*)&g_w[((size_t)b * N_ + t0 + t) * DIM_ + h * 64 + dq * 4];
        Kt[dq*4+0][t] = v.x; Kt[dq*4+1][t] = v.y;
        Kt[dq*4+2][t] = v.z; Kt[dq*4+3][t] = v.w;
    }
    __syncthreads();

    float acc[4][4] = {};
#pragma unroll 16
    for (int d = 0; d < 64; d++) {
        float4 qv = *(float4*)&Qt[d][4*ty];
        float4 kv = *(float4*)&Kt[d][4*tx];
        float qa[4] = {qv.x,qv.y,qv.z,qv.w};
        float ka[4] = {kv.x,kv.y,kv.z,kv.w};
#pragma unroll
        for (int i = 0; i < 4; i++)
#pragma unroll
            for (int j = 0; j < 4; j++) acc[i][j] += qa[i] * ka[j];
    }

    float* S = g_attn + (size_t)bh * 64 * N_;
    const float scale = 0.125f;
#pragma unroll
    for (int i = 0; i < 4; i++) {
        int q = 4*ty + i;
#pragma unroll
        for (int j = 0; j < 4; j++) {
            int t = t0 + 4*tx + j;
            if (t < N_) S[(size_t)q * N_ + t] = acc[i][j] * scale;
        }
    }
}

// ============================================================
// softmax over last dim (577)
// ============================================================
__global__ __launch_bounds__(256) void softmax_kernel()
{
    int bh = blockIdx.x;
    int w = threadIdx.x >> 5, lane = threadIdx.x & 31;
    for (int rr = 0; rr < 8; rr++) {
        int q = w * 8 + rr;
        float* p = g_attn + (size_t)bh * 64 * N_ + (size_t)q * N_;
        float v[19];
        float m = -INFINITY;
#pragma unroll
        for (int i = 0; i < 19; i++) {
            int idx = i * 32 + lane;
            v[i] = (idx < N_) ? p[idx] : -INFINITY;
            m = fmaxf(m, v[i]);
        }
#pragma unroll
        for (int o = 16; o > 0; o >>= 1) m = fmaxf(m, __shfl_xor_sync(0xffffffffu, m, o));
        float s = 0.f;
#pragma unroll
        for (int i = 0; i < 19; i++) { v[i] = __expf(v[i] - m); s += v[i]; }
#pragma unroll
        for (int o = 16; o > 0; o >>= 1) s += __shfl_xor_sync(0xffffffffu, s, o);
        float inv = 1.f / s;
#pragma unroll
        for (int i = 0; i < 19; i++) {
            int idx = i * 32 + lane;
            if (idx < N_) p[idx] = v[i] * inv;
        }
    }
}

// ============================================================
// rep_delta = P @ V;  rep += step_rep * rep_delta
// ============================================================
__global__ __launch_bounds__(256) void pv_kernel(const float* __restrict__ step_rep)
{
    __shared__ float Ps[64][68];
    __shared__ float Vs[64][64];
    int bh = blockIdx.x, b = bh >> 4, h = bh & 15;
    int tid = threadIdx.x, tx = tid & 15, ty = tid >> 4;
    const float* P = g_attn + (size_t)bh * 64 * N_;

    float acc[4][4] = {};
    for (int t0 = 0; t0 < N_; t0 += 64) {
        __syncthreads();
#pragma unroll
        for (int l = 0; l < 16; l++) {
            int f = tid + l * 256;
            int tl = f & 63, q = f >> 6;
            Ps[tl][q] = (t0 + tl < N_) ? P[(size_t)q * N_ + t0 + tl] : 0.f;
        }
#pragma unroll
        for (int l = 0; l < 4; l++) {
            int f = tid + l * 256;
            int t = f >> 4, dq = f & 15;
            float4 v = make_float4(0,0,0,0);
            if (t0 + t < N_)
                v = *(const float4*)&g_w[((size_t)b * N_ + t0 + t) * DIM_ + h * 64 + dq * 4];
            *(float4*)&Vs[t][dq * 4] = v;
        }
        __syncthreads();
#pragma unroll 16
        for (int t = 0; t < 64; t++) {
            float4 pv = *(float4*)&Ps[t][4*ty];
            float4 vv = *(float4*)&Vs[t][4*tx];
            float pa[4] = {pv.x,pv.y,pv.z,pv.w};
            float va[4] = {vv.x,vv.y,vv.z,vv.w};
#pragma unroll
            for (int i = 0; i < 4; i++)
#pragma unroll
                for (int j = 0; j < 4; j++) acc[i][j] += pa[i] * va[j];
        }
    }

    float step = step_rep[h];
    float* R = g_rep + (size_t)bh * 4096;
#pragma unroll
    for (int i = 0; i < 4; i++) {
        int q = 4*ty + i;
        float4 old = *(float4*)&R[q * 64 + 4*tx];
        old.x += step * acc[i][0]; old.y += step * acc[i][1];
        old.z += step * acc[i][2]; old.w += step * acc[i][3];
        *(float4*)&R[q * 64 + 4*tx] = old;
    }
}

// ============================================================
// attention-2 (self-attn of rep)
// ============================================================
__global__ __launch_bounds__(256) void attn2_kernel()
{
    __shared__ float Rt[64][64];
    __shared__ float Rn[64][64];
    __shared__ float Ss[64][64];
    int bh = blockIdx.x;
    int tid = threadIdx.x, tx = tid & 15, ty = tid >> 4;
    const float* R = g_rep + (size_t)bh * 4096;

#pragma unroll
    for (int l = 0; l < 4; l++) {
        int f = tid + l * 256;
        int q = f >> 4, dq = f & 15;
        float4 v = *(const float4*)&R[q * 64 + dq * 4];
        *(float4*)&Rn[q][dq * 4] = v;
        Rt[dq*4+0][q] = v.x; Rt[dq*4+1][q] = v.y;
        Rt[dq*4+2][q] = v.z; Rt[dq*4+3][q] = v.w;
    }
    __syncthreads();

    float acc[4][4] = {};
#pragma unroll 16
    for (int d = 0; d < 64; d++) {
        float4 qv = *(float4*)&Rt[d][4*ty];
        float4 kv = *(float4*)&Rt[d][4*tx];
        float qa[4] = {qv.x,qv.y,qv.z,qv.w};
        float ka[4] = {kv.x,kv.y,kv.z,kv.w};
#pragma unroll
        for (int i = 0; i < 4; i++)
#pragma unroll
            for (int j = 0; j < 4; j++) acc[i][j] += qa[i] * ka[j];
    }
    const float scale = 0.125f;
#pragma unroll
    for (int i = 0; i < 4; i++)
        *(float4*)&Ss[4*ty + i][4*tx] = make_float4(acc[i][0]*scale, acc[i][1]*scale,
                                                    acc[i][2]*scale, acc[i][3]*scale);
    __syncthreads();

    {
        int w = tid >> 5, lane = tid & 31;
        for (int rr = 0; rr < 8; rr++) {
            int q = w * 8 + rr;
            float v0 = Ss[q][lane], v1 = Ss[q][32 + lane];
            float m = fmaxf(v0, v1);
#pragma unroll
            for (int o = 16; o > 0; o >>= 1) m = fmaxf(m, __shfl_xor_sync(0xffffffffu, m, o));
            v0 = __expf(v0 - m); v1 = __expf(v1 - m);
            float s = v0 + v1;
#pragma unroll
            for (int o = 16; o > 0; o >>= 1) s += __shfl_xor_sync(0xffffffffu, s, o);
            float inv = 1.f / s;
            Ss[q][lane] = v0 * inv; Ss[q][32 + lane] = v1 * inv;
        }
    }
    __syncthreads();

    float acc2[4][4] = {};
#pragma unroll 16
    for (int k = 0; k < 64; k++) {
        float pv[4];
#pragma unroll
        for (int i = 0; i < 4; i++) pv[i] = Ss[4*ty + i][k];
        float4 rv = *(float4*)&Rn[k][4*tx];
        float ra[4] = {rv.x,rv.y,rv.z,rv.w};
#pragma unroll
        for (int i = 0; i < 4; i++)
#pragma unroll
            for (int j = 0; j < 4; j++) acc2[i][j] += pv[i] * ra[j];
    }
    float* O = g_out2 + (size_t)bh * 4096;
#pragma unroll
    for (int i = 0; i < 4; i++)
        *(float4*)&O[(4*ty + i) * 64 + 4*tx] = make_float4(acc2[i][0], acc2[i][1],
                                                           acc2[i][2], acc2[i][3]);
}

// ============================================================
// x_delta = step_x * (attn^T @ out2) -> written DIRECTLY as fp16 into g_ahi
// ============================================================
__global__ __launch_bounds__(256) void xdelta_kernel(const float* __restrict__ step_x)
{
    __shared__ float Ap[64][64];
    __shared__ float Os[64][64];
    int bh = blockIdx.y, b = bh >> 4, h = bh & 15;
    int t0 = blockIdx.x * 64;
    int tid = threadIdx.x, tx = tid & 15, ty = tid >> 4;
    const float* P  = g_attn + (size_t)bh * 64 * N_;
    const float* O2 = g_out2 + (size_t)bh * 4096;

#pragma unroll
    for (int l = 0; l < 16; l++) {
        int f = tid + l * 256;
        int tl = f & 63, p = f >> 6;
        Ap[p][tl] = (t0 + tl < N_) ? P[(size_t)p * N_ + t0 + tl] : 0.f;
    }
#pragma unroll
    for (int l = 0; l < 4; l++) {
        int f = tid + l * 256;
        int p = f >> 4, dq = f & 15;
        *(float4*)&Os[p][dq * 4] = *(const float4*)&O2[p * 64 + dq * 4];
    }
    __syncthreads();

    float acc[4][4] = {};
#pragma unroll 16
    for (int p = 0; p < 64; p++) {
        float4 av = *(float4*)&Ap[p][4*ty];
        float4 ov = *(float4*)&Os[p][4*tx];
        float aa[4] = {av.x,av.y,av.z,av.w};
        float oa[4] = {ov.x,ov.y,ov.z,ov.w};
#pragma unroll
        for (int i = 0; i < 4; i++)
#pragma unroll
            for (int j = 0; j < 4; j++) acc[i][j] += aa[i] * oa[j];
    }

    float step = step_x[h];
#pragma unroll
    for (int i = 0; i < 4; i++) {
        int t = t0 + 4*ty + i;
        if (t < N_) {
            __half2 h0 = __halves2half2(__float2half(step*acc[i][0]),
                                        __float2half(step*acc[i][1]));
            __half2 h1 = __halves2half2(__float2half(step*acc[i][2]),
                                        __float2half(step*acc[i][3]));
            uint2 u; u.x = *(unsigned*)&h0; u.y = *(unsigned*)&h1;
            *(uint2*)&g_ahi[((size_t)b * N_ + t) * DIM_ + h * 64 + 4*tx] = u;
        }
    }
}

// ============================================================
extern "C" void kernel_launch(void* const* d_in, const int* in_sizes, int n_in,
                              void* d_out, int out_size)
{
    (void)in_sizes; (void)n_in; (void)out_size;
    const float* x        = (const float*)d_in[0];
    const float* W_proj   = (const float*)d_in[1];
    const float* step_x   = (const float*)d_in[2];
    const float* step_rep = (const float*)d_in[3];
    const float* W_out    = (const float*)d_in[4];
    const float* b_out    = (const float*)d_in[5];
    float* out = (float*)d_out;

    cudaFuncSetAttribute(gemm_fp16_split,
                         cudaFuncAttributeMaxDynamicSharedMemorySize, GEMM_SMEM);

    dim3 gemm_grid(DIM_ / 128, M_ROWS / 128);   // (8, 577)

    split_a_hi<<<M_ROWS * DIM_ / 1024, 256>>>(x);           // x -> g_ahi (fp16)
    split_w_kernel<<<DIM_ * DIM_ / 1024, 256>>>(W_proj);    // -> whi/wlo
    gemm_fp16_split<<<gemm_grid, 128, GEMM_SMEM>>>(nullptr, nullptr);  // -> g_w
    pool_kernel<<<(BH_ * 64 * 64) / 256, 256>>>();
    qk_kernel<<<dim3(10, BH_), 256>>>();
    softmax_kernel<<<BH_, 256>>>();
    pv_kernel<<<BH_, 256>>>(step_rep);
    attn2_kernel<<<BH_, 256>>>();
    xdelta_kernel<<<dim3(10, BH_), 256>>>(step_x);          // -> g_ahi (fp16, fused split)
    split_w_kernel<<<DIM_ * DIM_ / 1024, 256>>>(W_out);
    gemm_fp16_split<<<gemm_grid, 128, GEMM_SMEM>>>(b_out, out);
}

// round 17
// speedup vs baseline: 3.3080x; 1.3799x over previous
#include <cuda_runtime.h>
#include <cuda_fp16.h>
#include <stdint.h>

#define B_   128
#define N_   577
#define DIM_ 1024
#define H_   16
#define BH_  (B_*H_)
#define M_ROWS (B_*N_)   // 73856

// ---- scratch (static device allocations; no cudaMalloc anywhere) ----
static __device__ float g_w[(size_t)M_ROWS*DIM_];      // w = x@Wp^T
static __device__ float g_attn[(size_t)BH_*64*N_];     // attention-1 probs
static __device__ float g_rep[(size_t)BH_*64*64];      // rep
static __device__ float g_out2[(size_t)BH_*64*64];     // attention-2 output
static __device__ __half g_ahi[(size_t)M_ROWS*DIM_];   // fp16 A operand (x, later x_delta)
static __device__ __half g_whi[(size_t)DIM_*DIM_];     // fp16 weight

// ============================================================
// warp-MMA helpers (sm_103-legal: ldmatrix + mma.sync fp16) — R14/15-proven
// ============================================================
__device__ __forceinline__ uint32_t smem_u32(const void* p) {
    return (uint32_t)__cvta_generic_to_shared(p);
}
__device__ __forceinline__ void ldsm_x4(uint32_t* r, uint32_t addr) {
    asm volatile("ldmatrix.sync.aligned.m8n8.x4.shared.b16 {%0,%1,%2,%3}, [%4];"
                 : "=r"(r[0]), "=r"(r[1]), "=r"(r[2]), "=r"(r[3]) : "r"(addr));
}
__device__ __forceinline__ void mma_fp16(float* c, const uint32_t* a, const uint32_t* b) {
    asm volatile("mma.sync.aligned.m16n8k16.row.col.f32.f16.f16.f32 "
                 "{%0,%1,%2,%3}, {%4,%5,%6,%7}, {%8,%9}, {%0,%1,%2,%3};"
                 : "+f"(c[0]), "+f"(c[1]), "+f"(c[2]), "+f"(c[3])
                 : "r"(a[0]), "r"(a[1]), "r"(a[2]), "r"(a[3]),
                   "r"(b[0]), "r"(b[1]));
}
#define CP16(dst, src) \
    asm volatile("cp.async.ca.shared.global [%0], [%1], 16;" :: "r"(dst), "l"(src) : "memory")
#define CP_COMMIT() asm volatile("cp.async.commit_group;" ::: "memory")

// ============================================================
// splits (fp16 hi only — residual terms dropped; see error model)
// ============================================================
__global__ __launch_bounds__(256) void split_a_hi(const float* __restrict__ src)
{
    size_t i = (size_t)blockIdx.x * 256 + threadIdx.x;   // one float4 each
    float4 v = ((const float4*)src)[i];
    __half2 p0 = __halves2half2(__float2half(v.x), __float2half(v.y));
    __half2 p1 = __halves2half2(__float2half(v.z), __float2half(v.w));
    uint2 u; u.x = *(unsigned*)&p0; u.y = *(unsigned*)&p1;
    ((uint2*)g_ahi)[i] = u;
}

__global__ __launch_bounds__(256) void split_w_hi(const float* __restrict__ src)
{
    size_t i = (size_t)blockIdx.x * 256 + threadIdx.x;
    float4 v = ((const float4*)src)[i];
    __half2 p0 = __halves2half2(__float2half(v.x), __float2half(v.y));
    __half2 p1 = __halves2half2(__float2half(v.z), __float2half(v.w));
    uint2 u; u.x = *(unsigned*)&p0; u.y = *(unsigned*)&p1;
    ((uint2*)g_whi)[i] = u;
}

// ============================================================
// fp16 tensor-core NT GEMM:  C[M,1024] = Ahi @ Whi^T (+bias)
// BM=BN=128, BK=32, 128 threads, warp tile 64x64 (4 warps), m16n8k16.
// cp.async 3-stage pipeline, 2 tiles/stage (Ahi, Whi).
// ============================================================
#define AROW 40                // 32 data + 8 pad halves/row; 80B stride (conflict-free)
#define TILE_B (128*AROW*2)    // 10240 bytes per tile
#define STAGE_B (2*TILE_B)     // 20480 per stage
#define GEMM_SMEM (3*STAGE_B)  // 61440

__global__ __launch_bounds__(128, 2) void gemm_fp16(const float* __restrict__ bias,
                                                    float* __restrict__ Cout)
{
    extern __shared__ __align__(16) __half sm[];
    float* C = Cout ? Cout : g_w;
    const int tid = threadIdx.x;
    const int m0 = blockIdx.y * 128, n0 = blockIdx.x * 128;
    const int lane = tid & 31, warp = tid >> 5;
    const int grp = lane >> 2, qid = lane & 3;
    const int wm0 = (warp >> 1) * 64;   // 2 warps on M
    const int wn0 = (warp & 1) * 64;    // 2 warps on N
    const uint32_t sbase = smem_u32(sm);

    float acc[4][8][4];
#pragma unroll
    for (int mi = 0; mi < 4; mi++)
#pragma unroll
        for (int n8 = 0; n8 < 8; n8++)
#pragma unroll
            for (int j = 0; j < 4; j++) acc[mi][n8][j] = 0.f;

    // stage issue: per tile 512 x 16B chunks; 128 threads x 4 chunks each
#define ISSUE_STAGE(s, kc) do {                                                   \
        const int kcol = (kc) * 32;                                               \
        const uint32_t st = sbase + (s) * STAGE_B;                                \
        _Pragma("unroll")                                                         \
        for (int i = 0; i < 4; i++) {                                             \
            int ch = i * 128 + tid;                                               \
            int row = ch >> 2, c16 = (ch & 3) * 8;                                \
            uint32_t so = (uint32_t)(row * AROW + c16) * 2;                       \
            CP16(st + 0*TILE_B + so, &g_ahi[(size_t)(m0 + row) * 1024 + kcol + c16]); \
            CP16(st + 1*TILE_B + so, &g_whi[(size_t)(n0 + row) * 1024 + kcol + c16]); \
        }                                                                         \
        CP_COMMIT();                                                              \
    } while (0)

    ISSUE_STAGE(0, 0);
    ISSUE_STAGE(1, 1);
    ISSUE_STAGE(2, 2);

    int s = 0;
    for (int kc = 0; kc < 32; kc++) {
        if (kc < 30)       asm volatile("cp.async.wait_group 2;" ::: "memory");
        else if (kc == 30) asm volatile("cp.async.wait_group 1;" ::: "memory");
        else               asm volatile("cp.async.wait_group 0;" ::: "memory");
        __syncthreads();

        const uint32_t stA = sbase + s * STAGE_B;
        const uint32_t stB = stA + TILE_B;
#pragma unroll
        for (int ks = 0; ks < 2; ks++) {
            const int kk = ks * 16;
            uint32_t ah[4][4], bh4[4][4];
#pragma unroll
            for (int mi = 0; mi < 4; mi++) {
                uint32_t ofs = (uint32_t)((wm0 + mi * 16 + (lane & 15)) * AROW
                                          + kk + 8 * (lane >> 4)) * 2;
                ldsm_x4(ah[mi], stA + ofs);
            }
#pragma unroll
            for (int nj = 0; nj < 4; nj++) {
                uint32_t ofs = (uint32_t)((wn0 + nj * 16 + (lane & 7) + ((lane >> 4) << 3)) * AROW
                                          + kk + 8 * ((lane >> 3) & 1)) * 2;
                ldsm_x4(bh4[nj], stB + ofs);
            }
#pragma unroll
            for (int mi = 0; mi < 4; mi++)
#pragma unroll
                for (int nj = 0; nj < 4; nj++)
#pragma unroll
                    for (int h = 0; h < 2; h++)
                        mma_fp16(acc[mi][nj * 2 + h], ah[mi], &bh4[nj][h * 2]);
        }
        __syncthreads();
        if (kc + 3 < 32) ISSUE_STAGE(s, kc + 3);
        s = (s == 2) ? 0 : s + 1;
    }
#undef ISSUE_STAGE

    // epilogue: c0/c1 @ (grp, 2qid/+1), c2/c3 @ (grp+8, ...)
#pragma unroll
    for (int mi = 0; mi < 4; mi++) {
        int r = m0 + wm0 + mi * 16 + grp;
#pragma unroll
        for (int n8 = 0; n8 < 8; n8++) {
            int c = n0 + wn0 + n8 * 8 + 2 * qid;
            float b0 = 0.f, b1 = 0.f;
            if (bias) { b0 = bias[c]; b1 = bias[c + 1]; }
            float* a = acc[mi][n8];
            *(float2*)&C[(size_t)r * 1024 + c]       = make_float2(a[0] + b0, a[1] + b1);
            *(float2*)&C[(size_t)(r + 8) * 1024 + c] = make_float2(a[2] + b0, a[3] + b1);
        }
    }
}

// ============================================================
// 3x3 adaptive mean pool -> rep0 (b,h,64,64)
// ============================================================
__global__ void pool_kernel()
{
    int idx = blockIdx.x * blockDim.x + threadIdx.x;
    int d  = idx & 63;
    int p  = (idx >> 6) & 63;
    int hh = (idx >> 12) & 15;
    int b  = idx >> 16;
    int py = p >> 3, px = p & 7;
    float s = 0.f;
#pragma unroll
    for (int r = 0; r < 3; r++)
#pragma unroll
        for (int c = 0; c < 3; c++) {
            int t = (3*py + r) * 24 + 3*px + c;
            s += g_w[((size_t)b * N_ + t) * DIM_ + hh * 64 + d];
        }
    g_rep[idx] = s * (1.f / 9.f);
}

// ============================================================
// attention-1 scores: S = scale * Q K^T
// ============================================================
__global__ __launch_bounds__(256) void qk_kernel()
{
    __shared__ float Qt[64][64];
    __shared__ float Kt[64][64];
    int bh = blockIdx.y;
    int b = bh >> 4, h = bh & 15;
    int t0 = blockIdx.x * 64;
    int tid = threadIdx.x, tx = tid & 15, ty = tid >> 4;

    const float* repb = g_rep + (size_t)bh * 4096;
#pragma unroll
    for (int l = 0; l < 4; l++) {
        int f = tid + l * 256;
        int q = f >> 4, dq = f & 15;
        float4 v = *(const float4*)&repb[q * 64 + dq * 4];
        Qt[dq*4+0][q] = v.x; Qt[dq*4+1][q] = v.y;
        Qt[dq*4+2][q] = v.z; Qt[dq*4+3][q] = v.w;
    }
#pragma unroll
    for (int l = 0; l < 4; l++) {
        int f = tid + l * 256;
        int t = f >> 4, dq = f & 15;
        float4 v = make_float4(0,0,0,0);
        if (t0 + t < N_)
            v = *(const float4*)&g_w[((size_t)b * N_ + t0 + t) * DIM_ + h * 64 + dq * 4];
        Kt[dq*4+0][t] = v.x; Kt[dq*4+1][t] = v.y;
        Kt[dq*4+2][t] = v.z; Kt[dq*4+3][t] = v.w;
    }
    __syncthreads();

    float acc[4][4] = {};
#pragma unroll 16
    for (int d = 0; d < 64; d++) {
        float4 qv = *(float4*)&Qt[d][4*ty];
        float4 kv = *(float4*)&Kt[d][4*tx];
        float qa[4] = {qv.x,qv.y,qv.z,qv.w};
        float ka[4] = {kv.x,kv.y,kv.z,kv.w};
#pragma unroll
        for (int i = 0; i < 4; i++)
#pragma unroll
            for (int j = 0; j < 4; j++) acc[i][j] += qa[i] * ka[j];
    }

    float* S = g_attn + (size_t)bh * 64 * N_;
    const float scale = 0.125f;
#pragma unroll
    for (int i = 0; i < 4; i++) {
        int q = 4*ty + i;
#pragma unroll
        for (int j = 0; j < 4; j++) {
            int t = t0 + 4*tx + j;
            if (t < N_) S[(size_t)q * N_ + t] = acc[i][j] * scale;
        }
    }
}

// ============================================================
// softmax over last dim (577)
// ============================================================
__global__ __launch_bounds__(256) void softmax_kernel()
{
    int bh = blockIdx.x;
    int w = threadIdx.x >> 5, lane = threadIdx.x & 31;
    for (int rr = 0; rr < 8; rr++) {
        int q = w * 8 + rr;
        float* p = g_attn + (size_t)bh * 64 * N_ + (size_t)q * N_;
        float v[19];
        float m = -INFINITY;
#pragma unroll
        for (int i = 0; i < 19; i++) {
            int idx = i * 32 + lane;
            v[i] = (idx < N_) ? p[idx] : -INFINITY;
            m = fmaxf(m, v[i]);
        }
#pragma unroll
        for (int o = 16; o > 0; o >>= 1) m = fmaxf(m, __shfl_xor_sync(0xffffffffu, m, o));
        float s = 0.f;
#pragma unroll
        for (int i = 0; i < 19; i++) { v[i] = __expf(v[i] - m); s += v[i]; }
#pragma unroll
        for (int o = 16; o > 0; o >>= 1) s += __shfl_xor_sync(0xffffffffu, s, o);
        float inv = 1.f / s;
#pragma unroll
        for (int i = 0; i < 19; i++) {
            int idx = i * 32 + lane;
            if (idx < N_) p[idx] = v[i] * inv;
        }
    }
}

// ============================================================
// rep_delta = P @ V;  rep += step_rep * rep_delta
// ============================================================
__global__ __launch_bounds__(256) void pv_kernel(const float* __restrict__ step_rep)
{
    __shared__ float Ps[64][68];
    __shared__ float Vs[64][64];
    int bh = blockIdx.x, b = bh >> 4, h = bh & 15;
    int tid = threadIdx.x, tx = tid & 15, ty = tid >> 4;
    const float* P = g_attn + (size_t)bh * 64 * N_;

    float acc[4][4] = {};
    for (int t0 = 0; t0 < N_; t0 += 64) {
        __syncthreads();
#pragma unroll
        for (int l = 0; l < 16; l++) {
            int f = tid + l * 256;
            int tl = f & 63, q = f >> 6;
            Ps[tl][q] = (t0 + tl < N_) ? P[(size_t)q * N_ + t0 + tl] : 0.f;
        }
#pragma unroll
        for (int l = 0; l < 4; l++) {
            int f = tid + l * 256;
            int t = f >> 4, dq = f & 15;
            float4 v = make_float4(0,0,0,0);
            if (t0 + t < N_)
                v = *(const float4*)&g_w[((size_t)b * N_ + t0 + t) * DIM_ + h * 64 + dq * 4];
            *(float4*)&Vs[t][dq * 4] = v;
        }
        __syncthreads();
#pragma unroll 16
        for (int t = 0; t < 64; t++) {
            float4 pv = *(float4*)&Ps[t][4*ty];
            float4 vv = *(float4*)&Vs[t][4*tx];
            float pa[4] = {pv.x,pv.y,pv.z,pv.w};
            float va[4] = {vv.x,vv.y,vv.z,vv.w};
#pragma unroll
            for (int i = 0; i < 4; i++)
#pragma unroll
                for (int j = 0; j < 4; j++) acc[i][j] += pa[i] * va[j];
        }
    }

    float step = step_rep[h];
    float* R = g_rep + (size_t)bh * 4096;
#pragma unroll
    for (int i = 0; i < 4; i++) {
        int q = 4*ty + i;
        float4 old = *(float4*)&R[q * 64 + 4*tx];
        old.x += step * acc[i][0]; old.y += step * acc[i][1];
        old.z += step * acc[i][2]; old.w += step * acc[i][3];
        *(float4*)&R[q * 64 + 4*tx] = old;
    }
}

// ============================================================
// attention-2 (self-attn of rep)
// ============================================================
__global__ __launch_bounds__(256) void attn2_kernel()
{
    __shared__ float Rt[64][64];
    __shared__ float Rn[64][64];
    __shared__ float Ss[64][64];
    int bh = blockIdx.x;
    int tid = threadIdx.x, tx = tid & 15, ty = tid >> 4;
    const float* R = g_rep + (size_t)bh * 4096;

#pragma unroll
    for (int l = 0; l < 4; l++) {
        int f = tid + l * 256;
        int q = f >> 4, dq = f & 15;
        float4 v = *(const float4*)&R[q * 64 + dq * 4];
        *(float4*)&Rn[q][dq * 4] = v;
        Rt[dq*4+0][q] = v.x; Rt[dq*4+1][q] = v.y;
        Rt[dq*4+2][q] = v.z; Rt[dq*4+3][q] = v.w;
    }
    __syncthreads();

    float acc[4][4] = {};
#pragma unroll 16
    for (int d = 0; d < 64; d++) {
        float4 qv = *(float4*)&Rt[d][4*ty];
        float4 kv = *(float4*)&Rt[d][4*tx];
        float qa[4] = {qv.x,qv.y,qv.z,qv.w};
        float ka[4] = {kv.x,kv.y,kv.z,kv.w};
#pragma unroll
        for (int i = 0; i < 4; i++)
#pragma unroll
            for (int j = 0; j < 4; j++) acc[i][j] += qa[i] * ka[j];
    }
    const float scale = 0.125f;
#pragma unroll
    for (int i = 0; i < 4; i++)
        *(float4*)&Ss[4*ty + i][4*tx] = make_float4(acc[i][0]*scale, acc[i][1]*scale,
                                                    acc[i][2]*scale, acc[i][3]*scale);
    __syncthreads();

    {
        int w = tid >> 5, lane = tid & 31;
        for (int rr = 0; rr < 8; rr++) {
            int q = w * 8 + rr;
            float v0 = Ss[q][lane], v1 = Ss[q][32 + lane];
            float m = fmaxf(v0, v1);
#pragma unroll
            for (int o = 16; o > 0; o >>= 1) m = fmaxf(m, __shfl_xor_sync(0xffffffffu, m, o));
            v0 = __expf(v0 - m); v1 = __expf(v1 - m);
            float s = v0 + v1;
#pragma unroll
            for (int o = 16; o > 0; o >>= 1) s += __shfl_xor_sync(0xffffffffu, s, o);
            float inv = 1.f / s;
            Ss[q][lane] = v0 * inv; Ss[q][32 + lane] = v1 * inv;
        }
    }
    __syncthreads();

    float acc2[4][4] = {};
#pragma unroll 16
    for (int k = 0; k < 64; k++) {
        float pv[4];
#pragma unroll
        for (int i = 0; i < 4; i++) pv[i] = Ss[4*ty + i][k];
        float4 rv = *(float4*)&Rn[k][4*tx];
        float ra[4] = {rv.x,rv.y,rv.z,rv.w};
#pragma unroll
        for (int i = 0; i < 4; i++)
#pragma unroll
            for (int j = 0; j < 4; j++) acc2[i][j] += pv[i] * ra[j];
    }
    float* O = g_out2 + (size_t)bh * 4096;
#pragma unroll
    for (int i = 0; i < 4; i++)
        *(float4*)&O[(4*ty + i) * 64 + 4*tx] = make_float4(acc2[i][0], acc2[i][1],
                                                           acc2[i][2], acc2[i][3]);
}

// ============================================================
// x_delta = step_x * (attn^T @ out2) -> written DIRECTLY as fp16 into g_ahi
// ============================================================
__global__ __launch_bounds__(256) void xdelta_kernel(const float* __restrict__ step_x)
{
    __shared__ float Ap[64][64];
    __shared__ float Os[64][64];
    int bh = blockIdx.y, b = bh >> 4, h = bh & 15;
    int t0 = blockIdx.x * 64;
    int tid = threadIdx.x, tx = tid & 15, ty = tid >> 4;
    const float* P  = g_attn + (size_t)bh * 64 * N_;
    const float* O2 = g_out2 + (size_t)bh * 4096;

#pragma unroll
    for (int l = 0; l < 16; l++) {
        int f = tid + l * 256;
        int tl = f & 63, p = f >> 6;
        Ap[p][tl] = (t0 + tl < N_) ? P[(size_t)p * N_ + t0 + tl] : 0.f;
    }
#pragma unroll
    for (int l = 0; l < 4; l++) {
        int f = tid + l * 256;
        int p = f >> 4, dq = f & 15;
        *(float4*)&Os[p][dq * 4] = *(const float4*)&O2[p * 64 + dq * 4];
    }
    __syncthreads();

    float acc[4][4] = {};
#pragma unroll 16
    for (int p = 0; p < 64; p++) {
        float4 av = *(float4*)&Ap[p][4*ty];
        float4 ov = *(float4*)&Os[p][4*tx];
        float aa[4] = {av.x,av.y,av.z,av.w};
        float oa[4] = {ov.x,ov.y,ov.z,ov.w};
#pragma unroll
        for (int i = 0; i < 4; i++)
#pragma unroll
            for (int j = 0; j < 4; j++) acc[i][j] += aa[i] * oa[j];
    }

    float step = step_x[h];
#pragma unroll
    for (int i = 0; i < 4; i++) {
        int t = t0 + 4*ty + i;
        if (t < N_) {
            __half2 h0 = __halves2half2(__float2half(step*acc[i][0]),
                                        __float2half(step*acc[i][1]));
            __half2 h1 = __halves2half2(__float2half(step*acc[i][2]),
                                        __float2half(step*acc[i][3]));
            uint2 u; u.x = *(unsigned*)&h0; u.y = *(unsigned*)&h1;
            *(uint2*)&g_ahi[((size_t)b * N_ + t) * DIM_ + h * 64 + 4*tx] = u;
        }
    }
}

// ============================================================
extern "C" void kernel_launch(void* const* d_in, const int* in_sizes, int n_in,
                              void* d_out, int out_size)
{
    (void)in_sizes; (void)n_in; (void)out_size;
    const float* x        = (const float*)d_in[0];
    const float* W_proj   = (const float*)d_in[1];
    const float* step_x   = (const float*)d_in[2];
    const float* step_rep = (const float*)d_in[3];
    const float* W_out    = (const float*)d_in[4];
    const float* b_out    = (const float*)d_in[5];
    float* out = (float*)d_out;

    cudaFuncSetAttribute(gemm_fp16,
                         cudaFuncAttributeMaxDynamicSharedMemorySize, GEMM_SMEM);

    dim3 gemm_grid(DIM_ / 128, M_ROWS / 128);   // (8, 577)

    split_a_hi<<<M_ROWS * DIM_ / 1024, 256>>>(x);           // x -> g_ahi (fp16)
    split_w_hi<<<DIM_ * DIM_ / 1024, 256>>>(W_proj);        // -> g_whi
    gemm_fp16<<<gemm_grid, 128, GEMM_SMEM>>>(nullptr, nullptr);  // -> g_w
    pool_kernel<<<(BH_ * 64 * 64) / 256, 256>>>();
    qk_kernel<<<dim3(10, BH_), 256>>>();
    softmax_kernel<<<BH_, 256>>>();
    pv_kernel<<<BH_, 256>>>(step_rep);
    attn2_kernel<<<BH_, 256>>>();
    xdelta_kernel<<<dim3(10, BH_), 256>>>(step_x);          // -> g_ahi (fp16, fused split)
    split_w_hi<<<DIM_ * DIM_ / 1024, 256>>>(W_out);
    gemm_fp16<<<gemm_grid, 128, GEMM_SMEM>>>(b_out, out);
}